// round 14
// baseline (speedup 1.0000x reference)
#include <cuda_runtime.h>
#include <cuda_fp16.h>
#include <math.h>
#include <stdint.h>

#define T_TOK 4096
#define HID 4096
#define NH 32
#define NKV 8
#define HD 128
#define BATCH 4
#define SEQ 1024
#define QKV_OUT 6144
#define EPSF 1e-6f
#define ATT_SCALE 0.08838834764831845f

// ---------------- scratch (device globals: allocation-free) ----------------
__device__ float g_qkv[(size_t)T_TOK * QKV_OUT];
__device__ float g_pool[BATCH * HD];
__device__ float g_gate[1];
__device__ float2 g_rope[SEQ * 64];              // (cos,sin) per (pos, j)
__device__ __half g_hid[(size_t)T_TOK * HID];
__device__ __half g_qw[(size_t)QKV_OUT * HID];   // transposed [N][K]
__device__ __half g_ow[(size_t)HID * HID];       // transposed [N][K]
__device__ __half g_qh[(size_t)T_TOK * NH * HD];
__device__ __half g_ql[(size_t)T_TOK * NH * HD];
__device__ __half g_kh[(size_t)T_TOK * NKV * HD];
__device__ __half g_kl[(size_t)T_TOK * NKV * HD];
__device__ __half g_v[(size_t)T_TOK * NKV * HD];
__device__ __half g_o[(size_t)T_TOK * NH * HD];

// ---------------- mma / ldmatrix / cp.async helpers ----------------
__device__ __forceinline__ uint32_t smem_u32(const void* p) {
    uint32_t a;
    asm("{ .reg .u64 t; cvta.to.shared.u64 t, %1; cvt.u32.u64 %0, t; }"
        : "=r"(a) : "l"(p));
    return a;
}
__device__ __forceinline__ void ldsm4(uint32_t* r, uint32_t addr) {
    asm volatile("ldmatrix.sync.aligned.m8n8.x4.shared.b16 {%0,%1,%2,%3}, [%4];"
        : "=r"(r[0]), "=r"(r[1]), "=r"(r[2]), "=r"(r[3]) : "r"(addr));
}
__device__ __forceinline__ void ldsm4t(uint32_t* r, uint32_t addr) {
    asm volatile("ldmatrix.sync.aligned.m8n8.x4.trans.shared.b16 {%0,%1,%2,%3}, [%4];"
        : "=r"(r[0]), "=r"(r[1]), "=r"(r[2]), "=r"(r[3]) : "r"(addr));
}
__device__ __forceinline__ void mma16816(float* c, const uint32_t* a,
                                         const uint32_t* b) {
    asm volatile("mma.sync.aligned.m16n8k16.row.col.f32.f16.f16.f32 "
        "{%0,%1,%2,%3}, {%4,%5,%6,%7}, {%8,%9}, {%0,%1,%2,%3};"
        : "+f"(c[0]), "+f"(c[1]), "+f"(c[2]), "+f"(c[3])
        : "r"(a[0]), "r"(a[1]), "r"(a[2]), "r"(a[3]), "r"(b[0]), "r"(b[1]));
}
__device__ __forceinline__ void cp16(uint32_t dst, const void* src) {
    asm volatile("cp.async.cg.shared.global [%0], [%1], 16;"
                 :: "r"(dst), "l"(src));
}
__device__ __forceinline__ void cp_commit() {
    asm volatile("cp.async.commit_group;" ::: "memory");
}
template <int N>
__device__ __forceinline__ void cp_wait() {
    asm volatile("cp.async.wait_group %0;" :: "n"(N) : "memory");
}
__device__ __forceinline__ uint32_t h2bits(float a, float b) {
    __half2 h = __floats2half2_rn(a, b);
    return *reinterpret_cast<uint32_t*>(&h);
}

// ---------------- conversion kernels ----------------
__global__ __launch_bounds__(256) void cvt_kernel(const float4* __restrict__ x,
                                                  __half* __restrict__ y, int n4) {
    int i = blockIdx.x * 256 + threadIdx.x;
    if (i < n4) {
        float4 v = x[i];
        uint2 o;
        o.x = h2bits(v.x, v.y);
        o.y = h2bits(v.z, v.w);
        *(uint2*)(y + (size_t)i * 4) = o;
    }
}

__global__ void cvt_T_kernel(const float* __restrict__ w,
                             __half* __restrict__ wT, int K, int N) {
    __shared__ __half sh[32][34];
    int tx = threadIdx.x, ty = threadIdx.y;
    int n0 = blockIdx.x * 32, k0 = blockIdx.y * 32;
    #pragma unroll
    for (int j = 0; j < 4; j++) {
        int k = k0 + ty + j * 8;
        sh[tx][ty + j * 8] = __float2half(w[(size_t)k * N + n0 + tx]);
    }
    __syncthreads();
    #pragma unroll
    for (int j = 0; j < 4; j++) {
        int n = n0 + ty + j * 8;
        wT[(size_t)n * K + k0 + tx] = sh[ty + j * 8][tx];
    }
}

__global__ void zero_pool_kernel(float* pool) {
    pool[threadIdx.x] = 0.0f;
}

// ---------------- RoPE table (pos x 64 freqs, double-reduced) ---------------
__global__ void rope_table_kernel(float2* __restrict__ rope) {
    int pos = blockIdx.x, j = threadIdx.x;   // 1024 x 64
    double invf = exp(-(double)j * (9.210340371976184 / 64.0));
    double ang = (double)pos * invf;
    const double TWO_PI = 6.283185307179586476925286766559;
    ang -= floor(ang * (1.0 / TWO_PI)) * TWO_PI;
    float c, s;
    sincosf((float)ang, &s, &c);
    rope[pos * 64 + j] = make_float2(c, s);
}

__device__ __forceinline__ void split_h(float f, __half& h, __half& l) {
    h = __float2half(f);
    l = __float2half(f - __half2float(h));
}

// ---------------- Q rmsnorm+rope v2: warp per (token, head) -----------------
// grid (T_TOK, NH/8), block 256 = 8 warps. Lane owns dims {d, d+32, d+64, d+96};
// rmsnorm = shfl reduce; RoPE pairs are in-register. No block barrier on the
// math path; pool via smem atomics + one global atomic per (block, d).
__global__ __launch_bounds__(256) void qnorm_v2(
    const float* __restrict__ qkv, const int* __restrict__ positions,
    const float* __restrict__ w, const float2* __restrict__ rope,
    __half* __restrict__ qh, __half* __restrict__ ql, float* __restrict__ pool) {
    int t = blockIdx.x;
    int h = blockIdx.y * 8 + (threadIdx.x >> 5);
    int lane = threadIdx.x & 31;
    int pos = positions[t];
    __shared__ float spool[128];
    for (int i = threadIdx.x; i < 128; i += 256) spool[i] = 0.0f;
    __syncthreads();

    const float* src = qkv + (size_t)t * QKV_OUT + h * HD;
    float x0 = src[lane], x1 = src[lane + 32], x2 = src[lane + 64], x3 = src[lane + 96];
    float ss = x0 * x0 + x1 * x1 + x2 * x2 + x3 * x3;
    #pragma unroll
    for (int o = 16; o > 0; o >>= 1) ss += __shfl_xor_sync(0xffffffffu, ss, o);
    float r = rsqrtf(ss * (1.0f / 128.0f) + EPSF);
    float n0 = x0 * r * w[lane];
    float n1 = x1 * r * w[lane + 32];
    float n2 = x2 * r * w[lane + 64];
    float n3 = x3 * r * w[lane + 96];
    atomicAdd(&spool[lane],      n0 + 0.0f);
    atomicAdd(&spool[lane + 32], n1 + 0.0f);
    atomicAdd(&spool[lane + 64], n2 + 0.0f);
    atomicAdd(&spool[lane + 96], n3 + 0.0f);
    float2 cs0 = rope[pos * 64 + lane];
    float2 cs1 = rope[pos * 64 + lane + 32];
    float o0 = n0 * cs0.x - n2 * cs0.y;
    float o2 = n2 * cs0.x + n0 * cs0.y;
    float o1 = n1 * cs1.x - n3 * cs1.y;
    float o3 = n3 * cs1.x + n1 * cs1.y;
    size_t base = (size_t)t * (NH * HD) + h * HD;
    __half hv, lv;
    split_h(o0, hv, lv); qh[base + lane] = hv;       ql[base + lane] = lv;
    split_h(o1, hv, lv); qh[base + lane + 32] = hv;  ql[base + lane + 32] = lv;
    split_h(o2, hv, lv); qh[base + lane + 64] = hv;  ql[base + lane + 64] = lv;
    split_h(o3, hv, lv); qh[base + lane + 96] = hv;  ql[base + lane + 96] = lv;
    __syncthreads();
    if (threadIdx.x < 128)
        atomicAdd(&pool[(t / SEQ) * 128 + threadIdx.x], spool[threadIdx.x]);
}

// ---------------- K rmsnorm+rope v2 + V convert -----------------------------
// grid (T_TOK), block 256 = 8 warps = 8 kv heads. Then V cvt (1024 floats).
__global__ __launch_bounds__(256) void knorm_v2(
    const float* __restrict__ qkv, const int* __restrict__ positions,
    const float* __restrict__ w, const float2* __restrict__ rope,
    __half* __restrict__ kh, __half* __restrict__ kl, __half* __restrict__ v) {
    int t = blockIdx.x;
    int h = threadIdx.x >> 5;
    int lane = threadIdx.x & 31;
    int pos = positions[t];

    const float* src = qkv + (size_t)t * QKV_OUT + NH * HD + h * HD;
    float x0 = src[lane], x1 = src[lane + 32], x2 = src[lane + 64], x3 = src[lane + 96];
    float ss = x0 * x0 + x1 * x1 + x2 * x2 + x3 * x3;
    #pragma unroll
    for (int o = 16; o > 0; o >>= 1) ss += __shfl_xor_sync(0xffffffffu, ss, o);
    float r = rsqrtf(ss * (1.0f / 128.0f) + EPSF);
    float n0 = x0 * r * w[lane];
    float n1 = x1 * r * w[lane + 32];
    float n2 = x2 * r * w[lane + 64];
    float n3 = x3 * r * w[lane + 96];
    float2 cs0 = rope[pos * 64 + lane];
    float2 cs1 = rope[pos * 64 + lane + 32];
    float o0 = n0 * cs0.x - n2 * cs0.y;
    float o2 = n2 * cs0.x + n0 * cs0.y;
    float o1 = n1 * cs1.x - n3 * cs1.y;
    float o3 = n3 * cs1.x + n1 * cs1.y;
    size_t base = (size_t)t * (NKV * HD) + h * HD;
    __half hv, lv;
    split_h(o0, hv, lv); kh[base + lane] = hv;       kl[base + lane] = lv;
    split_h(o1, hv, lv); kh[base + lane + 32] = hv;  kl[base + lane + 32] = lv;
    split_h(o2, hv, lv); kh[base + lane + 64] = hv;  kl[base + lane + 64] = lv;
    split_h(o3, hv, lv); kh[base + lane + 96] = hv;  kl[base + lane + 96] = lv;

    // V convert: 1024 floats = 256 float4, one per thread
    float4 vv = *(const float4*)(qkv + (size_t)t * QKV_OUT +
                                 (NH * HD + NKV * HD) + threadIdx.x * 4);
    uint2 o;
    o.x = h2bits(vv.x, vv.y);
    o.y = h2bits(vv.z, vv.w);
    *(uint2*)(v + (size_t)t * (NKV * HD) + threadIdx.x * 4) = o;
}

// ---------------- router gate ----------------
__device__ __forceinline__ float silu_f(float x) { return x / (1.0f + expf(-x)); }

__global__ __launch_bounds__(256) void router_kernel(
    const float* __restrict__ pool,
    const float* __restrict__ w1, const float* __restrict__ b1,
    const float* __restrict__ w2, const float* __restrict__ b2,
    const float* __restrict__ w3, const float* __restrict__ b3,
    const float* __restrict__ w4, const float* __restrict__ b4,
    const float* __restrict__ w5, const float* __restrict__ b5,
    float* __restrict__ gate) {
    __shared__ float pm[4][128];
    __shared__ float h1[4][1024];
    __shared__ float h2[4][256];
    __shared__ float h3[4][512];
    __shared__ float h4[4][128];
    __shared__ int anyflag;
    int tid = threadIdx.x;
    if (tid == 0) anyflag = 0;
    for (int idx = tid; idx < 512; idx += 256)
        pm[idx >> 7][idx & 127] = pool[idx] * (1.0f / 32768.0f);
    __syncthreads();
    for (int idx = tid; idx < 4096; idx += 256) {
        int b = idx >> 10, n = idx & 1023;
        float a = b1[n];
        for (int k = 0; k < 128; k++) a += pm[b][k] * w1[k * 1024 + n];
        h1[b][n] = silu_f(a);
    }
    __syncthreads();
    for (int idx = tid; idx < 1024; idx += 256) {
        int b = idx >> 8, n = idx & 255;
        float a = b2[n];
        for (int k = 0; k < 1024; k++) a += h1[b][k] * w2[k * 256 + n];
        h2[b][n] = a;
    }
    __syncthreads();
    for (int idx = tid; idx < 2048; idx += 256) {
        int b = idx >> 9, n = idx & 511;
        float a = b3[n];
        for (int k = 0; k < 256; k++) a += h2[b][k] * w3[k * 512 + n];
        h3[b][n] = silu_f(a);
    }
    __syncthreads();
    for (int idx = tid; idx < 512; idx += 256) {
        int b = idx >> 7, n = idx & 127;
        float a = b4[n];
        for (int k = 0; k < 512; k++) a += h3[b][k] * w4[k * 128 + n];
        h4[b][n] = silu_f(a);
    }
    __syncthreads();
    if (tid < 4) {
        float l0 = b5[0], l1 = b5[1];
        for (int k = 0; k < 128; k++) {
            l0 += h4[tid][k] * w5[k * 2 + 0];
            l1 += h4[tid][k] * w5[k * 2 + 1];
        }
        if (l1 > l0) anyflag = 1;
    }
    __syncthreads();
    if (tid == 0) gate[0] = anyflag ? 1.0f : 0.0f;
}

// ---------------- warp-MMA fp16 GEMM v5 (unchanged, 2 CTAs/SM) --------------
#define ROWB 144
#define ABUF (128 * ROWB)
#define STGB (2 * ABUF)
#define NSTG 3
#define GEMM_SMEM (NSTG * STGB)
__global__ __launch_bounds__(128, 2) void gemm_fp16_mma(
    const __half* __restrict__ A, const __half* __restrict__ B,
    float* __restrict__ C, int N, int K) {
    extern __shared__ __align__(16) char smem[];
    uint32_t sb = smem_u32(smem);
    int tid = threadIdx.x, wid = tid >> 5, lane = tid & 31;
    int wm = wid >> 1, wn = wid & 1;
    size_t bm = blockIdx.y, bn = blockIdx.x;
    int NT = K >> 6;

    int rA = tid >> 3, ch = tid & 7;
    const __half* srcA = A + (bm * 128 + rA) * (size_t)K + ch * 8;
    const __half* srcB = B + (bn * 128 + rA) * (size_t)K + ch * 8;
    uint32_t dA = (uint32_t)(rA * ROWB + ch * 16);

    uint32_t aoff = (uint32_t)((wm * 64 + (lane & 15)) * ROWB + ((lane >> 4) << 4));
    int g = lane >> 3;
    uint32_t boff = (uint32_t)((wn * 64 + ((g >> 1) << 3) + (lane & 7)) * ROWB +
                               ((g & 1) << 4));

    float acc[4][8][4];
    #pragma unroll
    for (int i = 0; i < 4; i++)
        #pragma unroll
        for (int j = 0; j < 8; j++)
            #pragma unroll
            for (int q = 0; q < 4; q++) acc[i][j][q] = 0.0f;

    #pragma unroll
    for (int pstg = 0; pstg < 2; pstg++) {
        uint32_t db = sb + pstg * STGB;
        #pragma unroll
        for (int i = 0; i < 8; i++) {
            cp16(db + dA + i * (16 * ROWB), srcA + (size_t)i * 16 * K);
            cp16(db + ABUF + dA + i * (16 * ROWB), srcB + (size_t)i * 16 * K);
        }
        srcA += 64; srcB += 64;
        cp_commit();
    }

    for (int kt = 0; kt < NT; kt++) {
        if (kt + 1 < NT) cp_wait<1>();
        else             cp_wait<0>();
        __syncthreads();
        if (kt + 2 < NT) {
            uint32_t db = sb + ((kt + 2) % 3) * STGB;
            #pragma unroll
            for (int i = 0; i < 8; i++) {
                cp16(db + dA + i * (16 * ROWB), srcA + (size_t)i * 16 * K);
                cp16(db + ABUF + dA + i * (16 * ROWB), srcB + (size_t)i * 16 * K);
            }
            srcA += 64; srcB += 64;
            cp_commit();
        }

        uint32_t sA = sb + (kt % 3) * STGB;
        uint32_t sB = sA + ABUF;

        #pragma unroll
        for (int ks = 0; ks < 4; ks++) {
            uint32_t kb = ks * 32;
            uint32_t af[4][4], bf[4][4];
            #pragma unroll
            for (int amt = 0; amt < 4; amt++)
                ldsm4(af[amt], sA + aoff + amt * (16 * ROWB) + kb);
            #pragma unroll
            for (int bnt = 0; bnt < 4; bnt++)
                ldsm4(bf[bnt], sB + boff + bnt * (16 * ROWB) + kb);
            #pragma unroll
            for (int amt = 0; amt < 4; amt++)
                #pragma unroll
                for (int bnt = 0; bnt < 4; bnt++) {
                    mma16816(acc[amt][2 * bnt],     af[amt], &bf[bnt][0]);
                    mma16816(acc[amt][2 * bnt + 1], af[amt], &bf[bnt][2]);
                }
        }
    }

    #pragma unroll
    for (int amt = 0; amt < 4; amt++) {
        size_t row = bm * 128 + wm * 64 + amt * 16 + (lane >> 2);
        #pragma unroll
        for (int bnt = 0; bnt < 4; bnt++)
            #pragma unroll
            for (int hh = 0; hh < 2; hh++) {
                size_t col = bn * 128 + wn * 64 + bnt * 16 + hh * 8 + (lane & 3) * 2;
                float* a4 = acc[amt][2 * bnt + hh];
                *(float2*)(C + row * N + col) = make_float2(a4[0], a4[1]);
                *(float2*)(C + (row + 8) * N + col) = make_float2(a4[2], a4[3]);
            }
    }
}

// ---------------- flash attention v4: 128 q-rows / CTA ----------------------
// 256 threads / 8 warps; warp w owns q rows [w*16, w*16+16). K/V tiles of 64
// keys serve all 128 rows (half the smem traffic of v3). K/V overlays the dead
// Q smem region after Q-fragment extraction.
#define AROW 272
#define QH_OFF 0
#define QL_OFF (128 * AROW)
#define KH_OFF 0
#define KL_OFF (64 * AROW)
#define V_OFF  (128 * AROW)
#define ATTN_SMEM (2 * 128 * AROW)   // 69632
__global__ __launch_bounds__(256, 1) void attn_mma_kernel(
    const __half* __restrict__ qh, const __half* __restrict__ ql,
    const __half* __restrict__ kh, const __half* __restrict__ kl,
    const __half* __restrict__ v, const float* __restrict__ gate,
    __half* __restrict__ oout) {
    extern __shared__ __align__(16) char smem[];
    uint32_t sb = smem_u32(smem);
    int qb = blockIdx.x;
    int bh = blockIdx.y;
    int b = bh >> 5, h = bh & 31;
    int kvh = h >> 2;
    int q0 = qb * 128;
    int tid = threadIdx.x, wid = tid >> 5, lane = tid & 31;

    // ---- load Q hi/lo (128 rows x 128 halves each) ----
    {
        int row = tid >> 4, ch = tid & 15;
        #pragma unroll
        for (int it = 0; it < 8; it++) {
            int rr = row + it * 16;
            size_t off = ((size_t)(b * SEQ + q0 + rr)) * (NH * HD) + h * HD + ch * 8;
            cp16(sb + QH_OFF + rr * AROW + ch * 16, qh + off);
            cp16(sb + QL_OFF + rr * AROW + ch * 16, ql + off);
        }
        cp_commit();
        cp_wait<0>();
    }
    __syncthreads();

    uint32_t qfh[8][4], qfl[8][4];
    {
        uint32_t aoffQ = (uint32_t)((wid * 16 + (lane & 15)) * AROW +
                                    ((lane >> 4) << 4));
        #pragma unroll
        for (int ks = 0; ks < 8; ks++) {
            ldsm4(qfh[ks], sb + QH_OFF + aoffQ + ks * 32);
            ldsm4(qfl[ks], sb + QL_OFF + aoffQ + ks * 32);
        }
    }
    __syncthreads();   // Q region dead; K/V may overwrite from here

    float of[16][4];
    #pragma unroll
    for (int i = 0; i < 16; i++)
        #pragma unroll
        for (int j = 0; j < 4; j++) of[i][j] = 0.0f;
    float m0 = -INFINITY, m1 = -INFINITY, l0 = 0.0f, l1 = 0.0f;
    int qi0 = q0 + wid * 16 + (lane >> 2);
    int qi1 = qi0 + 8;
    int numt = qb * 2 + 2;

    int g2 = lane >> 3;
    uint32_t boffK = (uint32_t)((((g2 >> 1) << 3) + (lane & 7)) * AROW +
                                ((g2 & 1) << 4));
    uint32_t vrow_base = (uint32_t)((((lane >> 3) & 1) * 8 + (lane & 7)) * AROW);
    uint32_t vcol_base = (uint32_t)((lane >> 4) << 4);

    for (int kt = 0; kt < numt; kt++) {
        int k0 = kt * 64;
        __syncthreads();
        {
            int row = tid >> 4, ch = tid & 15;
            #pragma unroll
            for (int it = 0; it < 4; it++) {
                int rr = row + it * 16;
                size_t off = ((size_t)(b * SEQ + k0 + rr)) * (NKV * HD) +
                             kvh * HD + ch * 8;
                cp16(sb + KH_OFF + rr * AROW + ch * 16, kh + off);
                cp16(sb + KL_OFF + rr * AROW + ch * 16, kl + off);
                cp16(sb + V_OFF + rr * AROW + ch * 16, v + off);
            }
            cp_commit();
            cp_wait<0>();
        }
        __syncthreads();

        float c[8][4];
        #pragma unroll
        for (int i = 0; i < 8; i++)
            #pragma unroll
            for (int j = 0; j < 4; j++) c[i][j] = 0.0f;
        #pragma unroll
        for (int ks = 0; ks < 8; ks++) {
            #pragma unroll
            for (int nf = 0; nf < 4; nf++) {
                uint32_t bh4[4], bl4[4];
                ldsm4(bh4, sb + KH_OFF + boffK + nf * (16 * AROW) + ks * 32);
                ldsm4(bl4, sb + KL_OFF + boffK + nf * (16 * AROW) + ks * 32);
                mma16816(c[nf * 2],     qfh[ks], bh4);
                mma16816(c[nf * 2 + 1], qfh[ks], bh4 + 2);
                mma16816(c[nf * 2],     qfh[ks], bl4);
                mma16816(c[nf * 2 + 1], qfh[ks], bl4 + 2);
                mma16816(c[nf * 2],     qfl[ks], bh4);
                mma16816(c[nf * 2 + 1], qfl[ks], bh4 + 2);
            }
        }

        bool domask = (k0 + 63 > qi0);
        #pragma unroll
        for (int f = 0; f < 8; f++) {
            int kk = k0 + f * 8 + (lane & 3) * 2;
            c[f][0] *= ATT_SCALE;
            c[f][1] *= ATT_SCALE;
            c[f][2] *= ATT_SCALE;
            c[f][3] *= ATT_SCALE;
            if (domask) {
                if (kk > qi0)     c[f][0] = -INFINITY;
                if (kk + 1 > qi0) c[f][1] = -INFINITY;
                if (kk > qi1)     c[f][2] = -INFINITY;
                if (kk + 1 > qi1) c[f][3] = -INFINITY;
            }
        }

        float mx0 = -INFINITY, mx1 = -INFINITY;
        #pragma unroll
        for (int f = 0; f < 8; f++) {
            mx0 = fmaxf(mx0, fmaxf(c[f][0], c[f][1]));
            mx1 = fmaxf(mx1, fmaxf(c[f][2], c[f][3]));
        }
        mx0 = fmaxf(mx0, __shfl_xor_sync(0xffffffffu, mx0, 1));
        mx0 = fmaxf(mx0, __shfl_xor_sync(0xffffffffu, mx0, 2));
        mx1 = fmaxf(mx1, __shfl_xor_sync(0xffffffffu, mx1, 1));
        mx1 = fmaxf(mx1, __shfl_xor_sync(0xffffffffu, mx1, 2));
        float mn0 = fmaxf(m0, mx0), mn1 = fmaxf(m1, mx1);
        float co0 = expf(m0 - mn0), co1 = expf(m1 - mn1);
        float s0 = 0.0f, s1 = 0.0f;
        #pragma unroll
        for (int f = 0; f < 8; f++) {
            c[f][0] = expf(c[f][0] - mn0); s0 += c[f][0];
            c[f][1] = expf(c[f][1] - mn0); s0 += c[f][1];
            c[f][2] = expf(c[f][2] - mn1); s1 += c[f][2];
            c[f][3] = expf(c[f][3] - mn1); s1 += c[f][3];
        }
        s0 += __shfl_xor_sync(0xffffffffu, s0, 1);
        s0 += __shfl_xor_sync(0xffffffffu, s0, 2);
        s1 += __shfl_xor_sync(0xffffffffu, s1, 1);
        s1 += __shfl_xor_sync(0xffffffffu, s1, 2);
        l0 = l0 * co0 + s0;
        l1 = l1 * co1 + s1;
        m0 = mn0;
        m1 = mn1;
        #pragma unroll
        for (int f = 0; f < 16; f++) {
            of[f][0] *= co0;
            of[f][1] *= co0;
            of[f][2] *= co1;
            of[f][3] *= co1;
        }

        #pragma unroll
        for (int ks2 = 0; ks2 < 4; ks2++) {
            uint32_t a[4];
            a[0] = h2bits(c[2 * ks2][0],     c[2 * ks2][1]);
            a[1] = h2bits(c[2 * ks2][2],     c[2 * ks2][3]);
            a[2] = h2bits(c[2 * ks2 + 1][0], c[2 * ks2 + 1][1]);
            a[3] = h2bits(c[2 * ks2 + 1][2], c[2 * ks2 + 1][3]);
            uint32_t vbase = sb + V_OFF + vrow_base + ks2 * (16 * AROW) + vcol_base;
            #pragma unroll
            for (int df = 0; df < 8; df++) {
                uint32_t vb[4];
                ldsm4t(vb, vbase + df * 32);
                mma16816(of[df * 2],     a, vb);
                mma16816(of[df * 2 + 1], a, vb + 2);
            }
        }
    }

    float gi = gate[0];
    float inv0 = gi / l0, inv1 = gi / l1;
    size_t base0 = ((size_t)(b * SEQ + qi0)) * (NH * HD) + h * HD;
    size_t base1 = base0 + (size_t)8 * (NH * HD);
    #pragma unroll
    for (int df = 0; df < 8; df++) {
        #pragma unroll
        for (int hh = 0; hh < 2; hh++) {
            int dim = df * 16 + hh * 8 + (lane & 3) * 2;
            float* o4 = of[df * 2 + hh];
            *(uint32_t*)(oout + base0 + dim) = h2bits(o4[0] * inv0, o4[1] * inv0);
            *(uint32_t*)(oout + base1 + dim) = h2bits(o4[2] * inv1, o4[3] * inv1);
        }
    }
}

// ---------------- launch ----------------
// gemm_fp16_mma (QKV) stays at launch index 3 for the harness ncu capture.
extern "C" void kernel_launch(void* const* d_in, const int* in_sizes, int n_in,
                              void* d_out, int out_size) {
    const float* hidden    = (const float*)d_in[0];
    const int*   positions = (const int*)d_in[1];
    const float* qkv_w = (const float*)d_in[3];
    const float* o_w   = (const float*)d_in[4];
    const float* qnw   = (const float*)d_in[5];
    const float* knw   = (const float*)d_in[6];
    const float* w1 = (const float*)d_in[7],  *b1 = (const float*)d_in[8];
    const float* w2 = (const float*)d_in[9],  *b2 = (const float*)d_in[10];
    const float* w3 = (const float*)d_in[11], *b3 = (const float*)d_in[12];
    const float* w4 = (const float*)d_in[13], *b4 = (const float*)d_in[14];
    const float* w5 = (const float*)d_in[15], *b5 = (const float*)d_in[16];
    float* out = (float*)d_out;

    float *qkv, *pool, *gate;
    float2* rope;
    __half *hidh, *qwh, *owh, *oh, *qhp, *qlp, *khp, *klp, *vp;
    cudaGetSymbolAddress((void**)&qkv,  g_qkv);
    cudaGetSymbolAddress((void**)&pool, g_pool);
    cudaGetSymbolAddress((void**)&gate, g_gate);
    cudaGetSymbolAddress((void**)&rope, g_rope);
    cudaGetSymbolAddress((void**)&hidh, g_hid);
    cudaGetSymbolAddress((void**)&qwh,  g_qw);
    cudaGetSymbolAddress((void**)&owh,  g_ow);
    cudaGetSymbolAddress((void**)&oh,   g_o);
    cudaGetSymbolAddress((void**)&qhp,  g_qh);
    cudaGetSymbolAddress((void**)&qlp,  g_ql);
    cudaGetSymbolAddress((void**)&khp,  g_kh);
    cudaGetSymbolAddress((void**)&klp,  g_kl);
    cudaGetSymbolAddress((void**)&vp,   g_v);

    cudaFuncSetAttribute(gemm_fp16_mma,
                         cudaFuncAttributeMaxDynamicSharedMemorySize, GEMM_SMEM);
    cudaFuncSetAttribute(attn_mma_kernel,
                         cudaFuncAttributeMaxDynamicSharedMemorySize, ATTN_SMEM);

    int n4_hid = (T_TOK * HID) / 4;
    cvt_kernel<<<n4_hid / 256, 256>>>((const float4*)hidden, hidh, n4_hid); // 0
    cvt_T_kernel<<<dim3(QKV_OUT / 32, HID / 32), dim3(32, 8)>>>(            // 1
        qkv_w, qwh, HID, QKV_OUT);
    cvt_T_kernel<<<dim3(HID / 32, HID / 32), dim3(32, 8)>>>(                // 2
        o_w, owh, HID, HID);

    gemm_fp16_mma<<<dim3(QKV_OUT / 128, T_TOK / 128), 128, GEMM_SMEM>>>(    // 3
        hidh, qwh, qkv, QKV_OUT, HID);

    rope_table_kernel<<<SEQ, 64>>>(rope);                                   // 4
    zero_pool_kernel<<<1, BATCH * HD>>>(pool);                              // 5
    qnorm_v2<<<dim3(T_TOK, NH / 8), 256>>>(qkv, positions, qnw, rope,       // 6
                                           qhp, qlp, pool);
    knorm_v2<<<T_TOK, 256>>>(qkv, positions, knw, rope, khp, klp, vp);      // 7
    router_kernel<<<1, 256>>>(pool, w1, b1, w2, b2, w3, b3, w4, b4, w5, b5, gate);
    attn_mma_kernel<<<dim3(SEQ / 128, BATCH * NH), 256, ATTN_SMEM>>>(       // 9
        qhp, qlp, khp, klp, vp, gate, oh);

    gemm_fp16_mma<<<dim3(HID / 128, T_TOK / 128), 128, GEMM_SMEM>>>(        // 10
        oh, owh, out, HID, HID);
}

// round 15
// speedup vs baseline: 1.0077x; 1.0077x over previous
#include <cuda_runtime.h>
#include <cuda_fp16.h>
#include <math.h>
#include <stdint.h>

#define T_TOK 4096
#define HID 4096
#define NH 32
#define NKV 8
#define HD 128
#define BATCH 4
#define SEQ 1024
#define QKV_OUT 6144
#define EPSF 1e-6f
#define ATT_SCALE 0.08838834764831845f

// ---------------- scratch (device globals: allocation-free) ----------------
__device__ float g_qkv[(size_t)T_TOK * QKV_OUT];
__device__ float g_pool[BATCH * HD];
__device__ float g_gate[1];
__device__ float2 g_rope[SEQ * 64];
__device__ __half g_hid[(size_t)T_TOK * HID];
__device__ __half g_qw[(size_t)QKV_OUT * HID];   // transposed [N][K]
__device__ __half g_ow[(size_t)HID * HID];       // transposed [N][K]
__device__ __half g_qh[(size_t)T_TOK * NH * HD];
__device__ __half g_ql[(size_t)T_TOK * NH * HD];
__device__ __half g_kh[(size_t)T_TOK * NKV * HD];
__device__ __half g_kl[(size_t)T_TOK * NKV * HD];
__device__ __half g_v[(size_t)T_TOK * NKV * HD];
__device__ __half g_o[(size_t)T_TOK * NH * HD];

// ---------------- mma / ldmatrix / cp.async helpers ----------------
__device__ __forceinline__ uint32_t smem_u32(const void* p) {
    uint32_t a;
    asm("{ .reg .u64 t; cvta.to.shared.u64 t, %1; cvt.u32.u64 %0, t; }"
        : "=r"(a) : "l"(p));
    return a;
}
__device__ __forceinline__ void ldsm4(uint32_t* r, uint32_t addr) {
    asm volatile("ldmatrix.sync.aligned.m8n8.x4.shared.b16 {%0,%1,%2,%3}, [%4];"
        : "=r"(r[0]), "=r"(r[1]), "=r"(r[2]), "=r"(r[3]) : "r"(addr));
}
__device__ __forceinline__ void ldsm4t(uint32_t* r, uint32_t addr) {
    asm volatile("ldmatrix.sync.aligned.m8n8.x4.trans.shared.b16 {%0,%1,%2,%3}, [%4];"
        : "=r"(r[0]), "=r"(r[1]), "=r"(r[2]), "=r"(r[3]) : "r"(addr));
}
__device__ __forceinline__ void mma16816(float* c, const uint32_t* a,
                                         const uint32_t* b) {
    asm volatile("mma.sync.aligned.m16n8k16.row.col.f32.f16.f16.f32 "
        "{%0,%1,%2,%3}, {%4,%5,%6,%7}, {%8,%9}, {%0,%1,%2,%3};"
        : "+f"(c[0]), "+f"(c[1]), "+f"(c[2]), "+f"(c[3])
        : "r"(a[0]), "r"(a[1]), "r"(a[2]), "r"(a[3]), "r"(b[0]), "r"(b[1]));
}
__device__ __forceinline__ void cp16(uint32_t dst, const void* src) {
    asm volatile("cp.async.cg.shared.global [%0], [%1], 16;"
                 :: "r"(dst), "l"(src));
}
__device__ __forceinline__ void cp_commit() {
    asm volatile("cp.async.commit_group;" ::: "memory");
}
template <int N>
__device__ __forceinline__ void cp_wait() {
    asm volatile("cp.async.wait_group %0;" :: "n"(N) : "memory");
}
__device__ __forceinline__ uint32_t h2bits(float a, float b) {
    __half2 h = __floats2half2_rn(a, b);
    return *reinterpret_cast<uint32_t*>(&h);
}

// ---------------- conversion kernels ----------------
__global__ __launch_bounds__(256) void cvt_kernel(const float4* __restrict__ x,
                                                  __half* __restrict__ y, int n4) {
    int i = blockIdx.x * 256 + threadIdx.x;
    if (i < n4) {
        float4 v = x[i];
        uint2 o;
        o.x = h2bits(v.x, v.y);
        o.y = h2bits(v.z, v.w);
        *(uint2*)(y + (size_t)i * 4) = o;
    }
}

__global__ void cvt_T_kernel(const float* __restrict__ w,
                             __half* __restrict__ wT, int K, int N) {
    __shared__ __half sh[32][34];
    int tx = threadIdx.x, ty = threadIdx.y;
    int n0 = blockIdx.x * 32, k0 = blockIdx.y * 32;
    #pragma unroll
    for (int j = 0; j < 4; j++) {
        int k = k0 + ty + j * 8;
        sh[tx][ty + j * 8] = __float2half(w[(size_t)k * N + n0 + tx]);
    }
    __syncthreads();
    #pragma unroll
    for (int j = 0; j < 4; j++) {
        int n = n0 + ty + j * 8;
        wT[(size_t)n * K + k0 + tx] = sh[ty + j * 8][tx];
    }
}

__global__ void zero_pool_kernel(float* pool) {
    pool[threadIdx.x] = 0.0f;
}

// ---------------- RoPE table ----------------
__global__ void rope_table_kernel(float2* __restrict__ rope) {
    int pos = blockIdx.x, j = threadIdx.x;
    double invf = exp(-(double)j * (9.210340371976184 / 64.0));
    double ang = (double)pos * invf;
    const double TWO_PI = 6.283185307179586476925286766559;
    ang -= floor(ang * (1.0 / TWO_PI)) * TWO_PI;
    float c, s;
    sincosf((float)ang, &s, &c);
    rope[pos * 64 + j] = make_float2(c, s);
}

__device__ __forceinline__ void split_h(float f, __half& h, __half& l) {
    h = __float2half(f);
    l = __float2half(f - __half2float(h));
}

// ---------------- Q rmsnorm+rope v2 ----------------
__global__ __launch_bounds__(256) void qnorm_v2(
    const float* __restrict__ qkv, const int* __restrict__ positions,
    const float* __restrict__ w, const float2* __restrict__ rope,
    __half* __restrict__ qh, __half* __restrict__ ql, float* __restrict__ pool) {
    int t = blockIdx.x;
    int h = blockIdx.y * 8 + (threadIdx.x >> 5);
    int lane = threadIdx.x & 31;
    int pos = positions[t];
    __shared__ float spool[128];
    for (int i = threadIdx.x; i < 128; i += 256) spool[i] = 0.0f;
    __syncthreads();

    const float* src = qkv + (size_t)t * QKV_OUT + h * HD;
    float x0 = src[lane], x1 = src[lane + 32], x2 = src[lane + 64], x3 = src[lane + 96];
    float ss = x0 * x0 + x1 * x1 + x2 * x2 + x3 * x3;
    #pragma unroll
    for (int o = 16; o > 0; o >>= 1) ss += __shfl_xor_sync(0xffffffffu, ss, o);
    float r = rsqrtf(ss * (1.0f / 128.0f) + EPSF);
    float n0 = x0 * r * w[lane];
    float n1 = x1 * r * w[lane + 32];
    float n2 = x2 * r * w[lane + 64];
    float n3 = x3 * r * w[lane + 96];
    atomicAdd(&spool[lane],      n0 + 0.0f);
    atomicAdd(&spool[lane + 32], n1 + 0.0f);
    atomicAdd(&spool[lane + 64], n2 + 0.0f);
    atomicAdd(&spool[lane + 96], n3 + 0.0f);
    float2 cs0 = rope[pos * 64 + lane];
    float2 cs1 = rope[pos * 64 + lane + 32];
    float o0 = n0 * cs0.x - n2 * cs0.y;
    float o2 = n2 * cs0.x + n0 * cs0.y;
    float o1 = n1 * cs1.x - n3 * cs1.y;
    float o3 = n3 * cs1.x + n1 * cs1.y;
    size_t base = (size_t)t * (NH * HD) + h * HD;
    __half hv, lv;
    split_h(o0, hv, lv); qh[base + lane] = hv;       ql[base + lane] = lv;
    split_h(o1, hv, lv); qh[base + lane + 32] = hv;  ql[base + lane + 32] = lv;
    split_h(o2, hv, lv); qh[base + lane + 64] = hv;  ql[base + lane + 64] = lv;
    split_h(o3, hv, lv); qh[base + lane + 96] = hv;  ql[base + lane + 96] = lv;
    __syncthreads();
    if (threadIdx.x < 128)
        atomicAdd(&pool[(t / SEQ) * 128 + threadIdx.x], spool[threadIdx.x]);
}

// ---------------- K rmsnorm+rope v2 + V convert ----------------
__global__ __launch_bounds__(256) void knorm_v2(
    const float* __restrict__ qkv, const int* __restrict__ positions,
    const float* __restrict__ w, const float2* __restrict__ rope,
    __half* __restrict__ kh, __half* __restrict__ kl, __half* __restrict__ v) {
    int t = blockIdx.x;
    int h = threadIdx.x >> 5;
    int lane = threadIdx.x & 31;
    int pos = positions[t];

    const float* src = qkv + (size_t)t * QKV_OUT + NH * HD + h * HD;
    float x0 = src[lane], x1 = src[lane + 32], x2 = src[lane + 64], x3 = src[lane + 96];
    float ss = x0 * x0 + x1 * x1 + x2 * x2 + x3 * x3;
    #pragma unroll
    for (int o = 16; o > 0; o >>= 1) ss += __shfl_xor_sync(0xffffffffu, ss, o);
    float r = rsqrtf(ss * (1.0f / 128.0f) + EPSF);
    float n0 = x0 * r * w[lane];
    float n1 = x1 * r * w[lane + 32];
    float n2 = x2 * r * w[lane + 64];
    float n3 = x3 * r * w[lane + 96];
    float2 cs0 = rope[pos * 64 + lane];
    float2 cs1 = rope[pos * 64 + lane + 32];
    float o0 = n0 * cs0.x - n2 * cs0.y;
    float o2 = n2 * cs0.x + n0 * cs0.y;
    float o1 = n1 * cs1.x - n3 * cs1.y;
    float o3 = n3 * cs1.x + n1 * cs1.y;
    size_t base = (size_t)t * (NKV * HD) + h * HD;
    __half hv, lv;
    split_h(o0, hv, lv); kh[base + lane] = hv;       kl[base + lane] = lv;
    split_h(o1, hv, lv); kh[base + lane + 32] = hv;  kl[base + lane + 32] = lv;
    split_h(o2, hv, lv); kh[base + lane + 64] = hv;  kl[base + lane + 64] = lv;
    split_h(o3, hv, lv); kh[base + lane + 96] = hv;  kl[base + lane + 96] = lv;

    float4 vv = *(const float4*)(qkv + (size_t)t * QKV_OUT +
                                 (NH * HD + NKV * HD) + threadIdx.x * 4);
    uint2 o;
    o.x = h2bits(vv.x, vv.y);
    o.y = h2bits(vv.z, vv.w);
    *(uint2*)(v + (size_t)t * (NKV * HD) + threadIdx.x * 4) = o;
}

// ---------------- router gate ----------------
__device__ __forceinline__ float silu_f(float x) { return x / (1.0f + expf(-x)); }

__global__ __launch_bounds__(256) void router_kernel(
    const float* __restrict__ pool,
    const float* __restrict__ w1, const float* __restrict__ b1,
    const float* __restrict__ w2, const float* __restrict__ b2,
    const float* __restrict__ w3, const float* __restrict__ b3,
    const float* __restrict__ w4, const float* __restrict__ b4,
    const float* __restrict__ w5, const float* __restrict__ b5,
    float* __restrict__ gate) {
    __shared__ float pm[4][128];
    __shared__ float h1[4][1024];
    __shared__ float h2[4][256];
    __shared__ float h3[4][512];
    __shared__ float h4[4][128];
    __shared__ int anyflag;
    int tid = threadIdx.x;
    if (tid == 0) anyflag = 0;
    for (int idx = tid; idx < 512; idx += 256)
        pm[idx >> 7][idx & 127] = pool[idx] * (1.0f / 32768.0f);
    __syncthreads();
    for (int idx = tid; idx < 4096; idx += 256) {
        int b = idx >> 10, n = idx & 1023;
        float a = b1[n];
        for (int k = 0; k < 128; k++) a += pm[b][k] * w1[k * 1024 + n];
        h1[b][n] = silu_f(a);
    }
    __syncthreads();
    for (int idx = tid; idx < 1024; idx += 256) {
        int b = idx >> 8, n = idx & 255;
        float a = b2[n];
        for (int k = 0; k < 1024; k++) a += h1[b][k] * w2[k * 256 + n];
        h2[b][n] = a;
    }
    __syncthreads();
    for (int idx = tid; idx < 2048; idx += 256) {
        int b = idx >> 9, n = idx & 511;
        float a = b3[n];
        for (int k = 0; k < 256; k++) a += h2[b][k] * w3[k * 512 + n];
        h3[b][n] = silu_f(a);
    }
    __syncthreads();
    for (int idx = tid; idx < 512; idx += 256) {
        int b = idx >> 7, n = idx & 127;
        float a = b4[n];
        for (int k = 0; k < 512; k++) a += h3[b][k] * w4[k * 128 + n];
        h4[b][n] = silu_f(a);
    }
    __syncthreads();
    if (tid < 4) {
        float l0 = b5[0], l1 = b5[1];
        for (int k = 0; k < 128; k++) {
            l0 += h4[tid][k] * w5[k * 2 + 0];
            l1 += h4[tid][k] * w5[k * 2 + 1];
        }
        if (l1 > l0) anyflag = 1;
    }
    __syncthreads();
    if (tid == 0) gate[0] = anyflag ? 1.0f : 0.0f;
}

// ---------------- warp-MMA fp16 GEMM v5 (unchanged) ----------------
#define ROWB 144
#define ABUF (128 * ROWB)
#define STGB (2 * ABUF)
#define NSTG 3
#define GEMM_SMEM (NSTG * STGB)
__global__ __launch_bounds__(128, 2) void gemm_fp16_mma(
    const __half* __restrict__ A, const __half* __restrict__ B,
    float* __restrict__ C, int N, int K) {
    extern __shared__ __align__(16) char smem[];
    uint32_t sb = smem_u32(smem);
    int tid = threadIdx.x, wid = tid >> 5, lane = tid & 31;
    int wm = wid >> 1, wn = wid & 1;
    size_t bm = blockIdx.y, bn = blockIdx.x;
    int NT = K >> 6;

    int rA = tid >> 3, ch = tid & 7;
    const __half* srcA = A + (bm * 128 + rA) * (size_t)K + ch * 8;
    const __half* srcB = B + (bn * 128 + rA) * (size_t)K + ch * 8;
    uint32_t dA = (uint32_t)(rA * ROWB + ch * 16);

    uint32_t aoff = (uint32_t)((wm * 64 + (lane & 15)) * ROWB + ((lane >> 4) << 4));
    int g = lane >> 3;
    uint32_t boff = (uint32_t)((wn * 64 + ((g >> 1) << 3) + (lane & 7)) * ROWB +
                               ((g & 1) << 4));

    float acc[4][8][4];
    #pragma unroll
    for (int i = 0; i < 4; i++)
        #pragma unroll
        for (int j = 0; j < 8; j++)
            #pragma unroll
            for (int q = 0; q < 4; q++) acc[i][j][q] = 0.0f;

    #pragma unroll
    for (int pstg = 0; pstg < 2; pstg++) {
        uint32_t db = sb + pstg * STGB;
        #pragma unroll
        for (int i = 0; i < 8; i++) {
            cp16(db + dA + i * (16 * ROWB), srcA + (size_t)i * 16 * K);
            cp16(db + ABUF + dA + i * (16 * ROWB), srcB + (size_t)i * 16 * K);
        }
        srcA += 64; srcB += 64;
        cp_commit();
    }

    for (int kt = 0; kt < NT; kt++) {
        if (kt + 1 < NT) cp_wait<1>();
        else             cp_wait<0>();
        __syncthreads();
        if (kt + 2 < NT) {
            uint32_t db = sb + ((kt + 2) % 3) * STGB;
            #pragma unroll
            for (int i = 0; i < 8; i++) {
                cp16(db + dA + i * (16 * ROWB), srcA + (size_t)i * 16 * K);
                cp16(db + ABUF + dA + i * (16 * ROWB), srcB + (size_t)i * 16 * K);
            }
            srcA += 64; srcB += 64;
            cp_commit();
        }

        uint32_t sA = sb + (kt % 3) * STGB;
        uint32_t sB = sA + ABUF;

        #pragma unroll
        for (int ks = 0; ks < 4; ks++) {
            uint32_t kb = ks * 32;
            uint32_t af[4][4], bf[4][4];
            #pragma unroll
            for (int amt = 0; amt < 4; amt++)
                ldsm4(af[amt], sA + aoff + amt * (16 * ROWB) + kb);
            #pragma unroll
            for (int bnt = 0; bnt < 4; bnt++)
                ldsm4(bf[bnt], sB + boff + bnt * (16 * ROWB) + kb);
            #pragma unroll
            for (int amt = 0; amt < 4; amt++)
                #pragma unroll
                for (int bnt = 0; bnt < 4; bnt++) {
                    mma16816(acc[amt][2 * bnt],     af[amt], &bf[bnt][0]);
                    mma16816(acc[amt][2 * bnt + 1], af[amt], &bf[bnt][2]);
                }
        }
    }

    #pragma unroll
    for (int amt = 0; amt < 4; amt++) {
        size_t row = bm * 128 + wm * 64 + amt * 16 + (lane >> 2);
        #pragma unroll
        for (int bnt = 0; bnt < 4; bnt++)
            #pragma unroll
            for (int hh = 0; hh < 2; hh++) {
                size_t col = bn * 128 + wn * 64 + bnt * 16 + hh * 8 + (lane & 3) * 2;
                float* a4 = acc[amt][2 * bnt + hh];
                *(float2*)(C + row * N + col) = make_float2(a4[0], a4[1]);
                *(float2*)(C + (row + 8) * N + col) = make_float2(a4[2], a4[3]);
            }
    }
}

// ---------------- flash attention v5: pipelined K/V double-buffer -----------
// 128 q-rows / CTA, 256 thr / 8 warps. K/V tiles of 64 keys, 2 stages
// (KH|KL|V = 51KB each) overlaying the dead Q region after frag extraction.
// Loads for tile kt+1 overlap compute of tile kt.
#define AROW 272
#define ATILE (64 * AROW)            // 17408 per operand tile
#define ASTG (3 * ATILE)             // 52224 per stage (KH,KL,V)
#define QH_OFF 0
#define QL_OFF (128 * AROW)          // 34816
#define ATTN_SMEM (2 * ASTG)         // 104448
__global__ __launch_bounds__(256, 1) void attn_mma_kernel(
    const __half* __restrict__ qh, const __half* __restrict__ ql,
    const __half* __restrict__ kh, const __half* __restrict__ kl,
    const __half* __restrict__ v, const float* __restrict__ gate,
    __half* __restrict__ oout) {
    extern __shared__ __align__(16) char smem[];
    uint32_t sb = smem_u32(smem);
    int qb = blockIdx.x;
    int bh = blockIdx.y;
    int b = bh >> 5, h = bh & 31;
    int kvh = h >> 2;
    int q0 = qb * 128;
    int tid = threadIdx.x, wid = tid >> 5, lane = tid & 31;
    int lrow = tid >> 4, lch = tid & 15;     // load map: 16 rows x 16 chunks

    // ---- load Q hi/lo (128 rows x 128 halves each) ----
    #pragma unroll
    for (int it = 0; it < 8; it++) {
        int rr = lrow + it * 16;
        size_t off = ((size_t)(b * SEQ + q0 + rr)) * (NH * HD) + h * HD + lch * 8;
        cp16(sb + QH_OFF + rr * AROW + lch * 16, qh + off);
        cp16(sb + QL_OFF + rr * AROW + lch * 16, ql + off);
    }
    cp_commit();
    cp_wait<0>();
    __syncthreads();

    // ---- Q fragments (registers for whole kernel) ----
    uint32_t qfh[8][4], qfl[8][4];
    {
        uint32_t aoffQ = (uint32_t)((wid * 16 + (lane & 15)) * AROW +
                                    ((lane >> 4) << 4));
        #pragma unroll
        for (int ks = 0; ks < 8; ks++) {
            ldsm4(qfh[ks], sb + QH_OFF + aoffQ + ks * 32);
            ldsm4(qfl[ks], sb + QL_OFF + aoffQ + ks * 32);
        }
    }
    __syncthreads();   // Q region dead; stages may overwrite from here

    float of[16][4];
    #pragma unroll
    for (int i = 0; i < 16; i++)
        #pragma unroll
        for (int j = 0; j < 4; j++) of[i][j] = 0.0f;
    float m0 = -INFINITY, m1 = -INFINITY, l0 = 0.0f, l1 = 0.0f;
    int qi0 = q0 + wid * 16 + (lane >> 2);
    int qi1 = qi0 + 8;
    int numt = qb * 2 + 2;

    int g2 = lane >> 3;
    uint32_t boffK = (uint32_t)((((g2 >> 1) << 3) + (lane & 7)) * AROW +
                                ((g2 & 1) << 4));
    uint32_t vrow_base = (uint32_t)((((lane >> 3) & 1) * 8 + (lane & 7)) * AROW);
    uint32_t vcol_base = (uint32_t)((lane >> 4) << 4);

    // ---- prologue: tile 0 -> stage 0 ----
    {
        uint32_t db = sb;
        #pragma unroll
        for (int it = 0; it < 4; it++) {
            int rr = lrow + it * 16;
            size_t off = ((size_t)(b * SEQ + rr)) * (NKV * HD) + kvh * HD + lch * 8;
            cp16(db + rr * AROW + lch * 16, kh + off);
            cp16(db + ATILE + rr * AROW + lch * 16, kl + off);
            cp16(db + 2 * ATILE + rr * AROW + lch * 16, v + off);
        }
        cp_commit();
    }

    for (int kt = 0; kt < numt; kt++) {
        int k0 = kt * 64;
        __syncthreads();   // all warps done computing tile kt-1 -> its stage reusable
        if (kt + 1 < numt) {
            uint32_t db = sb + ((kt + 1) & 1) * ASTG;
            int kn = (kt + 1) * 64;
            #pragma unroll
            for (int it = 0; it < 4; it++) {
                int rr = lrow + it * 16;
                size_t off = ((size_t)(b * SEQ + kn + rr)) * (NKV * HD) +
                             kvh * HD + lch * 8;
                cp16(db + rr * AROW + lch * 16, kh + off);
                cp16(db + ATILE + rr * AROW + lch * 16, kl + off);
                cp16(db + 2 * ATILE + rr * AROW + lch * 16, v + off);
            }
            cp_commit();
            cp_wait<1>();   // tile kt's group drained (only kt+1 pending)
        } else {
            cp_wait<0>();
        }
        __syncthreads();    // cross-thread visibility of tile kt data

        uint32_t stg = sb + (kt & 1) * ASTG;
        uint32_t sKH = stg, sKL = stg + ATILE, sV = stg + 2 * ATILE;

        float c[8][4];
        #pragma unroll
        for (int i = 0; i < 8; i++)
            #pragma unroll
            for (int j = 0; j < 4; j++) c[i][j] = 0.0f;
        #pragma unroll
        for (int ks = 0; ks < 8; ks++) {
            #pragma unroll
            for (int nf = 0; nf < 4; nf++) {
                uint32_t bh4[4], bl4[4];
                ldsm4(bh4, sKH + boffK + nf * (16 * AROW) + ks * 32);
                ldsm4(bl4, sKL + boffK + nf * (16 * AROW) + ks * 32);
                mma16816(c[nf * 2],     qfh[ks], bh4);
                mma16816(c[nf * 2 + 1], qfh[ks], bh4 + 2);
                mma16816(c[nf * 2],     qfh[ks], bl4);
                mma16816(c[nf * 2 + 1], qfh[ks], bl4 + 2);
                mma16816(c[nf * 2],     qfl[ks], bh4);
                mma16816(c[nf * 2 + 1], qfl[ks], bh4 + 2);
            }
        }

        bool domask = (k0 + 63 > qi0);
        #pragma unroll
        for (int f = 0; f < 8; f++) {
            int kk = k0 + f * 8 + (lane & 3) * 2;
            c[f][0] *= ATT_SCALE;
            c[f][1] *= ATT_SCALE;
            c[f][2] *= ATT_SCALE;
            c[f][3] *= ATT_SCALE;
            if (domask) {
                if (kk > qi0)     c[f][0] = -INFINITY;
                if (kk + 1 > qi0) c[f][1] = -INFINITY;
                if (kk > qi1)     c[f][2] = -INFINITY;
                if (kk + 1 > qi1) c[f][3] = -INFINITY;
            }
        }

        float mx0 = -INFINITY, mx1 = -INFINITY;
        #pragma unroll
        for (int f = 0; f < 8; f++) {
            mx0 = fmaxf(mx0, fmaxf(c[f][0], c[f][1]));
            mx1 = fmaxf(mx1, fmaxf(c[f][2], c[f][3]));
        }
        mx0 = fmaxf(mx0, __shfl_xor_sync(0xffffffffu, mx0, 1));
        mx0 = fmaxf(mx0, __shfl_xor_sync(0xffffffffu, mx0, 2));
        mx1 = fmaxf(mx1, __shfl_xor_sync(0xffffffffu, mx1, 1));
        mx1 = fmaxf(mx1, __shfl_xor_sync(0xffffffffu, mx1, 2));
        float mn0 = fmaxf(m0, mx0), mn1 = fmaxf(m1, mx1);
        float co0 = expf(m0 - mn0), co1 = expf(m1 - mn1);
        float s0 = 0.0f, s1 = 0.0f;
        #pragma unroll
        for (int f = 0; f < 8; f++) {
            c[f][0] = expf(c[f][0] - mn0); s0 += c[f][0];
            c[f][1] = expf(c[f][1] - mn0); s0 += c[f][1];
            c[f][2] = expf(c[f][2] - mn1); s1 += c[f][2];
            c[f][3] = expf(c[f][3] - mn1); s1 += c[f][3];
        }
        s0 += __shfl_xor_sync(0xffffffffu, s0, 1);
        s0 += __shfl_xor_sync(0xffffffffu, s0, 2);
        s1 += __shfl_xor_sync(0xffffffffu, s1, 1);
        s1 += __shfl_xor_sync(0xffffffffu, s1, 2);
        l0 = l0 * co0 + s0;
        l1 = l1 * co1 + s1;
        m0 = mn0;
        m1 = mn1;
        #pragma unroll
        for (int f = 0; f < 16; f++) {
            of[f][0] *= co0;
            of[f][1] *= co0;
            of[f][2] *= co1;
            of[f][3] *= co1;
        }

        #pragma unroll
        for (int ks2 = 0; ks2 < 4; ks2++) {
            uint32_t a[4];
            a[0] = h2bits(c[2 * ks2][0],     c[2 * ks2][1]);
            a[1] = h2bits(c[2 * ks2][2],     c[2 * ks2][3]);
            a[2] = h2bits(c[2 * ks2 + 1][0], c[2 * ks2 + 1][1]);
            a[3] = h2bits(c[2 * ks2 + 1][2], c[2 * ks2 + 1][3]);
            uint32_t vbase = sV + vrow_base + ks2 * (16 * AROW) + vcol_base;
            #pragma unroll
            for (int df = 0; df < 8; df++) {
                uint32_t vb[4];
                ldsm4t(vb, vbase + df * 32);
                mma16816(of[df * 2],     a, vb);
                mma16816(of[df * 2 + 1], a, vb + 2);
            }
        }
    }

    float gi = gate[0];
    float inv0 = gi / l0, inv1 = gi / l1;
    size_t base0 = ((size_t)(b * SEQ + qi0)) * (NH * HD) + h * HD;
    size_t base1 = base0 + (size_t)8 * (NH * HD);
    #pragma unroll
    for (int df = 0; df < 8; df++) {
        #pragma unroll
        for (int hh = 0; hh < 2; hh++) {
            int dim = df * 16 + hh * 8 + (lane & 3) * 2;
            float* o4 = of[df * 2 + hh];
            *(uint32_t*)(oout + base0 + dim) = h2bits(o4[0] * inv0, o4[1] * inv0);
            *(uint32_t*)(oout + base1 + dim) = h2bits(o4[2] * inv1, o4[3] * inv1);
        }
    }
}

// ---------------- launch ----------------
extern "C" void kernel_launch(void* const* d_in, const int* in_sizes, int n_in,
                              void* d_out, int out_size) {
    const float* hidden    = (const float*)d_in[0];
    const int*   positions = (const int*)d_in[1];
    const float* qkv_w = (const float*)d_in[3];
    const float* o_w   = (const float*)d_in[4];
    const float* qnw   = (const float*)d_in[5];
    const float* knw   = (const float*)d_in[6];
    const float* w1 = (const float*)d_in[7],  *b1 = (const float*)d_in[8];
    const float* w2 = (const float*)d_in[9],  *b2 = (const float*)d_in[10];
    const float* w3 = (const float*)d_in[11], *b3 = (const float*)d_in[12];
    const float* w4 = (const float*)d_in[13], *b4 = (const float*)d_in[14];
    const float* w5 = (const float*)d_in[15], *b5 = (const float*)d_in[16];
    float* out = (float*)d_out;

    float *qkv, *pool, *gate;
    float2* rope;
    __half *hidh, *qwh, *owh, *oh, *qhp, *qlp, *khp, *klp, *vp;
    cudaGetSymbolAddress((void**)&qkv,  g_qkv);
    cudaGetSymbolAddress((void**)&pool, g_pool);
    cudaGetSymbolAddress((void**)&gate, g_gate);
    cudaGetSymbolAddress((void**)&rope, g_rope);
    cudaGetSymbolAddress((void**)&hidh, g_hid);
    cudaGetSymbolAddress((void**)&qwh,  g_qw);
    cudaGetSymbolAddress((void**)&owh,  g_ow);
    cudaGetSymbolAddress((void**)&oh,   g_o);
    cudaGetSymbolAddress((void**)&qhp,  g_qh);
    cudaGetSymbolAddress((void**)&qlp,  g_ql);
    cudaGetSymbolAddress((void**)&khp,  g_kh);
    cudaGetSymbolAddress((void**)&klp,  g_kl);
    cudaGetSymbolAddress((void**)&vp,   g_v);

    cudaFuncSetAttribute(gemm_fp16_mma,
                         cudaFuncAttributeMaxDynamicSharedMemorySize, GEMM_SMEM);
    cudaFuncSetAttribute(attn_mma_kernel,
                         cudaFuncAttributeMaxDynamicSharedMemorySize, ATTN_SMEM);

    int n4_hid = (T_TOK * HID) / 4;
    cvt_kernel<<<n4_hid / 256, 256>>>((const float4*)hidden, hidh, n4_hid); // 0
    cvt_T_kernel<<<dim3(QKV_OUT / 32, HID / 32), dim3(32, 8)>>>(            // 1
        qkv_w, qwh, HID, QKV_OUT);
    cvt_T_kernel<<<dim3(HID / 32, HID / 32), dim3(32, 8)>>>(                // 2
        o_w, owh, HID, HID);

    gemm_fp16_mma<<<dim3(QKV_OUT / 128, T_TOK / 128), 128, GEMM_SMEM>>>(    // 3
        hidh, qwh, qkv, QKV_OUT, HID);

    rope_table_kernel<<<SEQ, 64>>>(rope);                                   // 4
    zero_pool_kernel<<<1, BATCH * HD>>>(pool);                              // 5
    qnorm_v2<<<dim3(T_TOK, NH / 8), 256>>>(qkv, positions, qnw, rope,       // 6
                                           qhp, qlp, pool);
    knorm_v2<<<T_TOK, 256>>>(qkv, positions, knw, rope, khp, klp, vp);      // 7
    router_kernel<<<1, 256>>>(pool, w1, b1, w2, b2, w3, b3, w4, b4, w5, b5, gate);
    attn_mma_kernel<<<dim3(SEQ / 128, BATCH * NH), 256, ATTN_SMEM>>>(       // 9
        qhp, qlp, khp, klp, vp, gate, oh);

    gemm_fp16_mma<<<dim3(HID / 128, T_TOK / 128), 128, GEMM_SMEM>>>(        // 10
        oh, owh, out, HID, HID);
}

// round 16
// speedup vs baseline: 1.0792x; 1.0710x over previous
#include <cuda_runtime.h>
#include <cuda_fp16.h>
#include <math.h>
#include <stdint.h>

#define T_TOK 4096
#define HID 4096
#define NH 32
#define NKV 8
#define HD 128
#define BATCH 4
#define SEQ 1024
#define QKV_OUT 6144
#define EPSF 1e-6f
#define ATT_SCALE 0.08838834764831845f

// ---------------- scratch (device globals: allocation-free) ----------------
__device__ float g_pool[BATCH * HD];
__device__ float g_gate[1];
__device__ float2 g_rope[SEQ * 64];
__device__ __half g_hid[(size_t)T_TOK * HID];
__device__ __half g_qw[(size_t)QKV_OUT * HID];    // transposed [N][K]
__device__ __half g_ow[(size_t)HID * HID];        // transposed [N][K]
__device__ __half g_qkvh[(size_t)T_TOK * QKV_OUT];// QKV gemm output (fp16)
__device__ __half g_qh[(size_t)T_TOK * NH * HD];  // q after norm+rope (fp16)
__device__ __half g_kh[(size_t)T_TOK * NKV * HD]; // k after norm+rope (fp16)
__device__ __half g_o[(size_t)T_TOK * NH * HD];   // attn out fp16

// ---------------- mma / ldmatrix / cp.async helpers ----------------
__device__ __forceinline__ uint32_t smem_u32(const void* p) {
    uint32_t a;
    asm("{ .reg .u64 t; cvta.to.shared.u64 t, %1; cvt.u32.u64 %0, t; }"
        : "=r"(a) : "l"(p));
    return a;
}
__device__ __forceinline__ void ldsm4(uint32_t* r, uint32_t addr) {
    asm volatile("ldmatrix.sync.aligned.m8n8.x4.shared.b16 {%0,%1,%2,%3}, [%4];"
        : "=r"(r[0]), "=r"(r[1]), "=r"(r[2]), "=r"(r[3]) : "r"(addr));
}
__device__ __forceinline__ void ldsm4t(uint32_t* r, uint32_t addr) {
    asm volatile("ldmatrix.sync.aligned.m8n8.x4.trans.shared.b16 {%0,%1,%2,%3}, [%4];"
        : "=r"(r[0]), "=r"(r[1]), "=r"(r[2]), "=r"(r[3]) : "r"(addr));
}
__device__ __forceinline__ void mma16816(float* c, const uint32_t* a,
                                         const uint32_t* b) {
    asm volatile("mma.sync.aligned.m16n8k16.row.col.f32.f16.f16.f32 "
        "{%0,%1,%2,%3}, {%4,%5,%6,%7}, {%8,%9}, {%0,%1,%2,%3};"
        : "+f"(c[0]), "+f"(c[1]), "+f"(c[2]), "+f"(c[3])
        : "r"(a[0]), "r"(a[1]), "r"(a[2]), "r"(a[3]), "r"(b[0]), "r"(b[1]));
}
__device__ __forceinline__ void cp16(uint32_t dst, const void* src) {
    asm volatile("cp.async.cg.shared.global [%0], [%1], 16;"
                 :: "r"(dst), "l"(src));
}
__device__ __forceinline__ void cp_commit() {
    asm volatile("cp.async.commit_group;" ::: "memory");
}
template <int N>
__device__ __forceinline__ void cp_wait() {
    asm volatile("cp.async.wait_group %0;" :: "n"(N) : "memory");
}
__device__ __forceinline__ uint32_t h2bits(float a, float b) {
    __half2 h = __floats2half2_rn(a, b);
    return *reinterpret_cast<uint32_t*>(&h);
}

// ---------------- cvt hidden -> fp16, + fused rope table & pool zero --------
__global__ __launch_bounds__(256) void cvt_kernel(const float4* __restrict__ x,
                                                  __half* __restrict__ y, int n4,
                                                  float2* __restrict__ rope,
                                                  float* __restrict__ pool) {
    int i = blockIdx.x * 256 + threadIdx.x;
    if (i < n4) {
        float4 v = x[i];
        uint2 o;
        o.x = h2bits(v.x, v.y);
        o.y = h2bits(v.z, v.w);
        *(uint2*)(y + (size_t)i * 4) = o;
    }
    // fused: rope table (first 256 blocks cover 1024*64 entries)
    if (blockIdx.x < 256) {
        int e = blockIdx.x * 256 + threadIdx.x;
        int pos = e >> 6, j = e & 63;
        double invf = exp(-(double)j * (9.210340371976184 / 64.0));
        double ang = (double)pos * invf;
        const double TWO_PI = 6.283185307179586476925286766559;
        ang -= floor(ang * (1.0 / TWO_PI)) * TWO_PI;
        float c, s;
        sincosf((float)ang, &s, &c);
        rope[e] = make_float2(c, s);
    }
    // fused: zero pool
    if (blockIdx.x == 300 && threadIdx.x < BATCH * HD) {
        pool[threadIdx.x] = 0.0f;
        pool[threadIdx.x + 256] = 0.0f;
    }
}

__global__ void cvt_T_kernel(const float* __restrict__ w,
                             __half* __restrict__ wT, int K, int N) {
    __shared__ __half sh[32][34];
    int tx = threadIdx.x, ty = threadIdx.y;
    int n0 = blockIdx.x * 32, k0 = blockIdx.y * 32;
    #pragma unroll
    for (int j = 0; j < 4; j++) {
        int k = k0 + ty + j * 8;
        sh[tx][ty + j * 8] = __float2half(w[(size_t)k * N + n0 + tx]);
    }
    __syncthreads();
    #pragma unroll
    for (int j = 0; j < 4; j++) {
        int n = n0 + ty + j * 8;
        wT[(size_t)n * K + k0 + tx] = sh[ty + j * 8][tx];
    }
}

// ---------------- Q rmsnorm+rope v3: fp16 in, fp16 out ----------------------
__global__ __launch_bounds__(256) void qnorm_v3(
    const __half* __restrict__ qkv, const int* __restrict__ positions,
    const float* __restrict__ w, const float2* __restrict__ rope,
    __half* __restrict__ qh, float* __restrict__ pool) {
    int t = blockIdx.x;
    int h = blockIdx.y * 8 + (threadIdx.x >> 5);
    int lane = threadIdx.x & 31;
    int pos = positions[t];
    __shared__ float spool[128];
    for (int i = threadIdx.x; i < 128; i += 256) spool[i] = 0.0f;
    __syncthreads();

    const __half* src = qkv + (size_t)t * QKV_OUT + h * HD;
    float x0 = __half2float(src[lane]);
    float x1 = __half2float(src[lane + 32]);
    float x2 = __half2float(src[lane + 64]);
    float x3 = __half2float(src[lane + 96]);
    float ss = x0 * x0 + x1 * x1 + x2 * x2 + x3 * x3;
    #pragma unroll
    for (int o = 16; o > 0; o >>= 1) ss += __shfl_xor_sync(0xffffffffu, ss, o);
    float r = rsqrtf(ss * (1.0f / 128.0f) + EPSF);
    float n0 = x0 * r * w[lane];
    float n1 = x1 * r * w[lane + 32];
    float n2 = x2 * r * w[lane + 64];
    float n3 = x3 * r * w[lane + 96];
    atomicAdd(&spool[lane],      n0);
    atomicAdd(&spool[lane + 32], n1);
    atomicAdd(&spool[lane + 64], n2);
    atomicAdd(&spool[lane + 96], n3);
    float2 cs0 = rope[pos * 64 + lane];
    float2 cs1 = rope[pos * 64 + lane + 32];
    float o0 = n0 * cs0.x - n2 * cs0.y;
    float o2 = n2 * cs0.x + n0 * cs0.y;
    float o1 = n1 * cs1.x - n3 * cs1.y;
    float o3 = n3 * cs1.x + n1 * cs1.y;
    size_t base = (size_t)t * (NH * HD) + h * HD;
    qh[base + lane]      = __float2half(o0);
    qh[base + lane + 32] = __float2half(o1);
    qh[base + lane + 64] = __float2half(o2);
    qh[base + lane + 96] = __float2half(o3);
    __syncthreads();
    if (threadIdx.x < 128)
        atomicAdd(&pool[(t / SEQ) * 128 + threadIdx.x], spool[threadIdx.x]);
}

// ---------------- K rmsnorm+rope v3: fp16 in, fp16 out ----------------------
__global__ __launch_bounds__(256) void knorm_v3(
    const __half* __restrict__ qkv, const int* __restrict__ positions,
    const float* __restrict__ w, const float2* __restrict__ rope,
    __half* __restrict__ kh) {
    int t = blockIdx.x;
    int h = threadIdx.x >> 5;
    int lane = threadIdx.x & 31;
    int pos = positions[t];

    const __half* src = qkv + (size_t)t * QKV_OUT + NH * HD + h * HD;
    float x0 = __half2float(src[lane]);
    float x1 = __half2float(src[lane + 32]);
    float x2 = __half2float(src[lane + 64]);
    float x3 = __half2float(src[lane + 96]);
    float ss = x0 * x0 + x1 * x1 + x2 * x2 + x3 * x3;
    #pragma unroll
    for (int o = 16; o > 0; o >>= 1) ss += __shfl_xor_sync(0xffffffffu, ss, o);
    float r = rsqrtf(ss * (1.0f / 128.0f) + EPSF);
    float n0 = x0 * r * w[lane];
    float n1 = x1 * r * w[lane + 32];
    float n2 = x2 * r * w[lane + 64];
    float n3 = x3 * r * w[lane + 96];
    float2 cs0 = rope[pos * 64 + lane];
    float2 cs1 = rope[pos * 64 + lane + 32];
    float o0 = n0 * cs0.x - n2 * cs0.y;
    float o2 = n2 * cs0.x + n0 * cs0.y;
    float o1 = n1 * cs1.x - n3 * cs1.y;
    float o3 = n3 * cs1.x + n1 * cs1.y;
    size_t base = (size_t)t * (NKV * HD) + h * HD;
    kh[base + lane]      = __float2half(o0);
    kh[base + lane + 32] = __float2half(o1);
    kh[base + lane + 64] = __float2half(o2);
    kh[base + lane + 96] = __float2half(o3);
}

// ---------------- router gate ----------------
__device__ __forceinline__ float silu_f(float x) { return x / (1.0f + expf(-x)); }

__global__ __launch_bounds__(256) void router_kernel(
    const float* __restrict__ pool,
    const float* __restrict__ w1, const float* __restrict__ b1,
    const float* __restrict__ w2, const float* __restrict__ b2,
    const float* __restrict__ w3, const float* __restrict__ b3,
    const float* __restrict__ w4, const float* __restrict__ b4,
    const float* __restrict__ w5, const float* __restrict__ b5,
    float* __restrict__ gate) {
    __shared__ float pm[4][128];
    __shared__ float h1[4][1024];
    __shared__ float h2[4][256];
    __shared__ float h3[4][512];
    __shared__ float h4[4][128];
    __shared__ int anyflag;
    int tid = threadIdx.x;
    if (tid == 0) anyflag = 0;
    for (int idx = tid; idx < 512; idx += 256)
        pm[idx >> 7][idx & 127] = pool[idx] * (1.0f / 32768.0f);
    __syncthreads();
    for (int idx = tid; idx < 4096; idx += 256) {
        int b = idx >> 10, n = idx & 1023;
        float a = b1[n];
        for (int k = 0; k < 128; k++) a += pm[b][k] * w1[k * 1024 + n];
        h1[b][n] = silu_f(a);
    }
    __syncthreads();
    for (int idx = tid; idx < 1024; idx += 256) {
        int b = idx >> 8, n = idx & 255;
        float a = b2[n];
        for (int k = 0; k < 1024; k++) a += h1[b][k] * w2[k * 256 + n];
        h2[b][n] = a;
    }
    __syncthreads();
    for (int idx = tid; idx < 2048; idx += 256) {
        int b = idx >> 9, n = idx & 511;
        float a = b3[n];
        for (int k = 0; k < 256; k++) a += h2[b][k] * w3[k * 512 + n];
        h3[b][n] = silu_f(a);
    }
    __syncthreads();
    for (int idx = tid; idx < 512; idx += 256) {
        int b = idx >> 7, n = idx & 127;
        float a = b4[n];
        for (int k = 0; k < 512; k++) a += h3[b][k] * w4[k * 128 + n];
        h4[b][n] = silu_f(a);
    }
    __syncthreads();
    if (tid < 4) {
        float l0 = b5[0], l1 = b5[1];
        for (int k = 0; k < 128; k++) {
            l0 += h4[tid][k] * w5[k * 2 + 0];
            l1 += h4[tid][k] * w5[k * 2 + 1];
        }
        if (l1 > l0) anyflag = 1;
    }
    __syncthreads();
    if (tid == 0) gate[0] = anyflag ? 1.0f : 0.0f;
}

// ---------------- warp-MMA fp16 GEMM v6 (optional fp16 output) --------------
#define ROWB 144
#define ABUF (128 * ROWB)
#define STGB (2 * ABUF)
#define NSTG 3
#define GEMM_SMEM (NSTG * STGB)
__global__ __launch_bounds__(128, 2) void gemm_fp16_mma(
    const __half* __restrict__ A, const __half* __restrict__ B,
    void* __restrict__ C, int N, int K, int halfout) {
    extern __shared__ __align__(16) char smem[];
    uint32_t sb = smem_u32(smem);
    int tid = threadIdx.x, wid = tid >> 5, lane = tid & 31;
    int wm = wid >> 1, wn = wid & 1;
    size_t bm = blockIdx.y, bn = blockIdx.x;
    int NT = K >> 6;

    int rA = tid >> 3, ch = tid & 7;
    const __half* srcA = A + (bm * 128 + rA) * (size_t)K + ch * 8;
    const __half* srcB = B + (bn * 128 + rA) * (size_t)K + ch * 8;
    uint32_t dA = (uint32_t)(rA * ROWB + ch * 16);

    uint32_t aoff = (uint32_t)((wm * 64 + (lane & 15)) * ROWB + ((lane >> 4) << 4));
    int g = lane >> 3;
    uint32_t boff = (uint32_t)((wn * 64 + ((g >> 1) << 3) + (lane & 7)) * ROWB +
                               ((g & 1) << 4));

    float acc[4][8][4];
    #pragma unroll
    for (int i = 0; i < 4; i++)
        #pragma unroll
        for (int j = 0; j < 8; j++)
            #pragma unroll
            for (int q = 0; q < 4; q++) acc[i][j][q] = 0.0f;

    #pragma unroll
    for (int pstg = 0; pstg < 2; pstg++) {
        uint32_t db = sb + pstg * STGB;
        #pragma unroll
        for (int i = 0; i < 8; i++) {
            cp16(db + dA + i * (16 * ROWB), srcA + (size_t)i * 16 * K);
            cp16(db + ABUF + dA + i * (16 * ROWB), srcB + (size_t)i * 16 * K);
        }
        srcA += 64; srcB += 64;
        cp_commit();
    }

    for (int kt = 0; kt < NT; kt++) {
        if (kt + 1 < NT) cp_wait<1>();
        else             cp_wait<0>();
        __syncthreads();
        if (kt + 2 < NT) {
            uint32_t db = sb + ((kt + 2) % 3) * STGB;
            #pragma unroll
            for (int i = 0; i < 8; i++) {
                cp16(db + dA + i * (16 * ROWB), srcA + (size_t)i * 16 * K);
                cp16(db + ABUF + dA + i * (16 * ROWB), srcB + (size_t)i * 16 * K);
            }
            srcA += 64; srcB += 64;
            cp_commit();
        }

        uint32_t sA = sb + (kt % 3) * STGB;
        uint32_t sB = sA + ABUF;

        #pragma unroll
        for (int ks = 0; ks < 4; ks++) {
            uint32_t kb = ks * 32;
            uint32_t af[4][4], bf[4][4];
            #pragma unroll
            for (int amt = 0; amt < 4; amt++)
                ldsm4(af[amt], sA + aoff + amt * (16 * ROWB) + kb);
            #pragma unroll
            for (int bnt = 0; bnt < 4; bnt++)
                ldsm4(bf[bnt], sB + boff + bnt * (16 * ROWB) + kb);
            #pragma unroll
            for (int amt = 0; amt < 4; amt++)
                #pragma unroll
                for (int bnt = 0; bnt < 4; bnt++) {
                    mma16816(acc[amt][2 * bnt],     af[amt], &bf[bnt][0]);
                    mma16816(acc[amt][2 * bnt + 1], af[amt], &bf[bnt][2]);
                }
        }
    }

    if (halfout) {
        __half* Ch = (__half*)C;
        #pragma unroll
        for (int amt = 0; amt < 4; amt++) {
            size_t row = bm * 128 + wm * 64 + amt * 16 + (lane >> 2);
            #pragma unroll
            for (int bnt = 0; bnt < 4; bnt++)
                #pragma unroll
                for (int hh = 0; hh < 2; hh++) {
                    size_t col = bn * 128 + wn * 64 + bnt * 16 + hh * 8 +
                                 (lane & 3) * 2;
                    float* a4 = acc[amt][2 * bnt + hh];
                    *(uint32_t*)(Ch + row * N + col) = h2bits(a4[0], a4[1]);
                    *(uint32_t*)(Ch + (row + 8) * N + col) = h2bits(a4[2], a4[3]);
                }
        }
    } else {
        float* Cf = (float*)C;
        #pragma unroll
        for (int amt = 0; amt < 4; amt++) {
            size_t row = bm * 128 + wm * 64 + amt * 16 + (lane >> 2);
            #pragma unroll
            for (int bnt = 0; bnt < 4; bnt++)
                #pragma unroll
                for (int hh = 0; hh < 2; hh++) {
                    size_t col = bn * 128 + wn * 64 + bnt * 16 + hh * 8 +
                                 (lane & 3) * 2;
                    float* a4 = acc[amt][2 * bnt + hh];
                    *(float2*)(Cf + row * N + col) = make_float2(a4[0], a4[1]);
                    *(float2*)(Cf + (row + 8) * N + col) = make_float2(a4[2], a4[3]);
                }
        }
    }
}

// ---------------- flash attention v6: 1-product scores, pipelined -----------
// 128 q-rows / CTA, 256 thr / 8 warps. K/V tiles of 64 keys, 2 stages (K|V).
// V read directly from the fp16 qkv buffer (stride QKV_OUT).
#define AROW 272
#define ATILE (64 * AROW)            // 17408 per operand tile
#define ASTG (2 * ATILE)             // 34816 per stage (K, V)
#define ATTN_SMEM (2 * ASTG)         // 69632  (Q region 34816 overlaid)
__global__ __launch_bounds__(256, 1) void attn_mma_kernel(
    const __half* __restrict__ qh, const __half* __restrict__ kh,
    const __half* __restrict__ qkvh, const float* __restrict__ gate,
    __half* __restrict__ oout) {
    extern __shared__ __align__(16) char smem[];
    uint32_t sb = smem_u32(smem);
    int qb = blockIdx.x;
    int bh = blockIdx.y;
    int b = bh >> 5, h = bh & 31;
    int kvh = h >> 2;
    int q0 = qb * 128;
    int tid = threadIdx.x, wid = tid >> 5, lane = tid & 31;
    int lrow = tid >> 4, lch = tid & 15;

    // ---- load Q (128 rows x 128 halves) ----
    #pragma unroll
    for (int it = 0; it < 8; it++) {
        int rr = lrow + it * 16;
        size_t off = ((size_t)(b * SEQ + q0 + rr)) * (NH * HD) + h * HD + lch * 8;
        cp16(sb + rr * AROW + lch * 16, qh + off);
    }
    cp_commit();
    cp_wait<0>();
    __syncthreads();

    uint32_t qf[8][4];
    {
        uint32_t aoffQ = (uint32_t)((wid * 16 + (lane & 15)) * AROW +
                                    ((lane >> 4) << 4));
        #pragma unroll
        for (int ks = 0; ks < 8; ks++)
            ldsm4(qf[ks], sb + aoffQ + ks * 32);
    }
    __syncthreads();   // Q region dead; stages overwrite from here

    float of[16][4];
    #pragma unroll
    for (int i = 0; i < 16; i++)
        #pragma unroll
        for (int j = 0; j < 4; j++) of[i][j] = 0.0f;
    float m0 = -INFINITY, m1 = -INFINITY, l0 = 0.0f, l1 = 0.0f;
    int qi0 = q0 + wid * 16 + (lane >> 2);
    int qi1 = qi0 + 8;
    int numt = qb * 2 + 2;

    int g2 = lane >> 3;
    uint32_t boffK = (uint32_t)((((g2 >> 1) << 3) + (lane & 7)) * AROW +
                                ((g2 & 1) << 4));
    uint32_t vrow_base = (uint32_t)((((lane >> 3) & 1) * 8 + (lane & 7)) * AROW);
    uint32_t vcol_base = (uint32_t)((lane >> 4) << 4);

    const __half* vsrc = qkvh + (NH * HD + NKV * HD) + kvh * HD;

    // ---- prologue: tile 0 -> stage 0 ----
    #pragma unroll
    for (int it = 0; it < 4; it++) {
        int rr = lrow + it * 16;
        cp16(sb + rr * AROW + lch * 16,
             kh + ((size_t)(b * SEQ + rr)) * (NKV * HD) + kvh * HD + lch * 8);
        cp16(sb + ATILE + rr * AROW + lch * 16,
             vsrc + ((size_t)(b * SEQ + rr)) * QKV_OUT + lch * 8);
    }
    cp_commit();

    for (int kt = 0; kt < numt; kt++) {
        int k0 = kt * 64;
        __syncthreads();   // compute of kt-1 done -> its stage reusable
        if (kt + 1 < numt) {
            uint32_t db = sb + ((kt + 1) & 1) * ASTG;
            int kn = (kt + 1) * 64;
            #pragma unroll
            for (int it = 0; it < 4; it++) {
                int rr = lrow + it * 16;
                cp16(db + rr * AROW + lch * 16,
                     kh + ((size_t)(b * SEQ + kn + rr)) * (NKV * HD) +
                     kvh * HD + lch * 8);
                cp16(db + ATILE + rr * AROW + lch * 16,
                     vsrc + ((size_t)(b * SEQ + kn + rr)) * QKV_OUT + lch * 8);
            }
            cp_commit();
            cp_wait<1>();
        } else {
            cp_wait<0>();
        }
        __syncthreads();

        uint32_t stg = sb + (kt & 1) * ASTG;
        uint32_t sK = stg, sV = stg + ATILE;

        float c[8][4];
        #pragma unroll
        for (int i = 0; i < 8; i++)
            #pragma unroll
            for (int j = 0; j < 4; j++) c[i][j] = 0.0f;
        #pragma unroll
        for (int ks = 0; ks < 8; ks++) {
            #pragma unroll
            for (int nf = 0; nf < 4; nf++) {
                uint32_t bh4[4];
                ldsm4(bh4, sK + boffK + nf * (16 * AROW) + ks * 32);
                mma16816(c[nf * 2],     qf[ks], bh4);
                mma16816(c[nf * 2 + 1], qf[ks], bh4 + 2);
            }
        }

        bool domask = (k0 + 63 > qi0);
        #pragma unroll
        for (int f = 0; f < 8; f++) {
            int kk = k0 + f * 8 + (lane & 3) * 2;
            c[f][0] *= ATT_SCALE;
            c[f][1] *= ATT_SCALE;
            c[f][2] *= ATT_SCALE;
            c[f][3] *= ATT_SCALE;
            if (domask) {
                if (kk > qi0)     c[f][0] = -INFINITY;
                if (kk + 1 > qi0) c[f][1] = -INFINITY;
                if (kk > qi1)     c[f][2] = -INFINITY;
                if (kk + 1 > qi1) c[f][3] = -INFINITY;
            }
        }

        float mx0 = -INFINITY, mx1 = -INFINITY;
        #pragma unroll
        for (int f = 0; f < 8; f++) {
            mx0 = fmaxf(mx0, fmaxf(c[f][0], c[f][1]));
            mx1 = fmaxf(mx1, fmaxf(c[f][2], c[f][3]));
        }
        mx0 = fmaxf(mx0, __shfl_xor_sync(0xffffffffu, mx0, 1));
        mx0 = fmaxf(mx0, __shfl_xor_sync(0xffffffffu, mx0, 2));
        mx1 = fmaxf(mx1, __shfl_xor_sync(0xffffffffu, mx1, 1));
        mx1 = fmaxf(mx1, __shfl_xor_sync(0xffffffffu, mx1, 2));
        float mn0 = fmaxf(m0, mx0), mn1 = fmaxf(m1, mx1);
        float co0 = expf(m0 - mn0), co1 = expf(m1 - mn1);
        float s0 = 0.0f, s1 = 0.0f;
        #pragma unroll
        for (int f = 0; f < 8; f++) {
            c[f][0] = expf(c[f][0] - mn0); s0 += c[f][0];
            c[f][1] = expf(c[f][1] - mn0); s0 += c[f][1];
            c[f][2] = expf(c[f][2] - mn1); s1 += c[f][2];
            c[f][3] = expf(c[f][3] - mn1); s1 += c[f][3];
        }
        s0 += __shfl_xor_sync(0xffffffffu, s0, 1);
        s0 += __shfl_xor_sync(0xffffffffu, s0, 2);
        s1 += __shfl_xor_sync(0xffffffffu, s1, 1);
        s1 += __shfl_xor_sync(0xffffffffu, s1, 2);
        l0 = l0 * co0 + s0;
        l1 = l1 * co1 + s1;
        m0 = mn0;
        m1 = mn1;
        #pragma unroll
        for (int f = 0; f < 16; f++) {
            of[f][0] *= co0;
            of[f][1] *= co0;
            of[f][2] *= co1;
            of[f][3] *= co1;
        }

        #pragma unroll
        for (int ks2 = 0; ks2 < 4; ks2++) {
            uint32_t a[4];
            a[0] = h2bits(c[2 * ks2][0],     c[2 * ks2][1]);
            a[1] = h2bits(c[2 * ks2][2],     c[2 * ks2][3]);
            a[2] = h2bits(c[2 * ks2 + 1][0], c[2 * ks2 + 1][1]);
            a[3] = h2bits(c[2 * ks2 + 1][2], c[2 * ks2 + 1][3]);
            uint32_t vbase = sV + vrow_base + ks2 * (16 * AROW) + vcol_base;
            #pragma unroll
            for (int df = 0; df < 8; df++) {
                uint32_t vb[4];
                ldsm4t(vb, vbase + df * 32);
                mma16816(of[df * 2],     a, vb);
                mma16816(of[df * 2 + 1], a, vb + 2);
            }
        }
    }

    float gi = gate[0];
    float inv0 = gi / l0, inv1 = gi / l1;
    size_t base0 = ((size_t)(b * SEQ + qi0)) * (NH * HD) + h * HD;
    size_t base1 = base0 + (size_t)8 * (NH * HD);
    #pragma unroll
    for (int df = 0; df < 8; df++) {
        #pragma unroll
        for (int hh = 0; hh < 2; hh++) {
            int dim = df * 16 + hh * 8 + (lane & 3) * 2;
            float* o4 = of[df * 2 + hh];
            *(uint32_t*)(oout + base0 + dim) = h2bits(o4[0] * inv0, o4[1] * inv0);
            *(uint32_t*)(oout + base1 + dim) = h2bits(o4[2] * inv1, o4[3] * inv1);
        }
    }
}

// ---------------- launch ----------------
// qnorm_v3 now sits at launch index 3 -> profiled by the harness next round.
extern "C" void kernel_launch(void* const* d_in, const int* in_sizes, int n_in,
                              void* d_out, int out_size) {
    const float* hidden    = (const float*)d_in[0];
    const int*   positions = (const int*)d_in[1];
    const float* qkv_w = (const float*)d_in[3];
    const float* o_w   = (const float*)d_in[4];
    const float* qnw   = (const float*)d_in[5];
    const float* knw   = (const float*)d_in[6];
    const float* w1 = (const float*)d_in[7],  *b1 = (const float*)d_in[8];
    const float* w2 = (const float*)d_in[9],  *b2 = (const float*)d_in[10];
    const float* w3 = (const float*)d_in[11], *b3 = (const float*)d_in[12];
    const float* w4 = (const float*)d_in[13], *b4 = (const float*)d_in[14];
    const float* w5 = (const float*)d_in[15], *b5 = (const float*)d_in[16];
    float* out = (float*)d_out;

    float *pool, *gate;
    float2* rope;
    __half *hidh, *qwh, *owh, *qkvh, *qhp, *khp, *oh;
    cudaGetSymbolAddress((void**)&pool, g_pool);
    cudaGetSymbolAddress((void**)&gate, g_gate);
    cudaGetSymbolAddress((void**)&rope, g_rope);
    cudaGetSymbolAddress((void**)&hidh, g_hid);
    cudaGetSymbolAddress((void**)&qwh,  g_qw);
    cudaGetSymbolAddress((void**)&owh,  g_ow);
    cudaGetSymbolAddress((void**)&qkvh, g_qkvh);
    cudaGetSymbolAddress((void**)&qhp,  g_qh);
    cudaGetSymbolAddress((void**)&khp,  g_kh);
    cudaGetSymbolAddress((void**)&oh,   g_o);

    cudaFuncSetAttribute(gemm_fp16_mma,
                         cudaFuncAttributeMaxDynamicSharedMemorySize, GEMM_SMEM);
    cudaFuncSetAttribute(attn_mma_kernel,
                         cudaFuncAttributeMaxDynamicSharedMemorySize, ATTN_SMEM);

    int n4_hid = (T_TOK * HID) / 4;
    cvt_kernel<<<n4_hid / 256, 256>>>((const float4*)hidden, hidh, n4_hid,  // 0
                                      rope, pool);
    cvt_T_kernel<<<dim3(QKV_OUT / 32, HID / 32), dim3(32, 8)>>>(            // 1
        qkv_w, qwh, HID, QKV_OUT);

    gemm_fp16_mma<<<dim3(QKV_OUT / 128, T_TOK / 128), 128, GEMM_SMEM>>>(    // 2
        hidh, qwh, qkvh, QKV_OUT, HID, 1);

    qnorm_v3<<<dim3(T_TOK, NH / 8), 256>>>(qkvh, positions, qnw, rope,      // 3
                                           qhp, pool);
    knorm_v3<<<T_TOK, 256>>>(qkvh, positions, knw, rope, khp);              // 4
    cvt_T_kernel<<<dim3(HID / 32, HID / 32), dim3(32, 8)>>>(                // 5
        o_w, owh, HID, HID);
    router_kernel<<<1, 256>>>(pool, w1, b1, w2, b2, w3, b3, w4, b4, w5, b5, gate);
    attn_mma_kernel<<<dim3(SEQ / 128, BATCH * NH), 256, ATTN_SMEM>>>(       // 7
        qhp, khp, qkvh, gate, oh);

    gemm_fp16_mma<<<dim3(HID / 128, T_TOK / 128), 128, GEMM_SMEM>>>(        // 8
        oh, owh, out, HID, HID, 0);
}

// round 17
// speedup vs baseline: 1.0873x; 1.0075x over previous
#include <cuda_runtime.h>
#include <cuda_fp16.h>
#include <math.h>
#include <stdint.h>

#define T_TOK 4096
#define HID 4096
#define NH 32
#define NKV 8
#define HD 128
#define BATCH 4
#define SEQ 1024
#define QKV_OUT 6144
#define EPSF 1e-6f
#define ATT_SCALE 0.08838834764831845f

// ---------------- scratch (device globals: allocation-free) ----------------
__device__ float g_pool[BATCH * HD];
__device__ float g_gate[1];
__device__ float2 g_rope[SEQ * 64];
__device__ __half g_hid[(size_t)T_TOK * HID];
__device__ __half g_qw[(size_t)QKV_OUT * HID];    // transposed [N][K]
__device__ __half g_ow[(size_t)HID * HID];        // transposed [N][K]
__device__ __half g_qkvh[(size_t)T_TOK * QKV_OUT];// QKV gemm output (fp16)
__device__ __half g_qh[(size_t)T_TOK * NH * HD];  // q after norm+rope (fp16)
__device__ __half g_kh[(size_t)T_TOK * NKV * HD]; // k after norm+rope (fp16)
__device__ __half g_o[(size_t)T_TOK * NH * HD];   // attn out fp16

// ---------------- mma / ldmatrix / cp.async helpers ----------------
__device__ __forceinline__ uint32_t smem_u32(const void* p) {
    uint32_t a;
    asm("{ .reg .u64 t; cvta.to.shared.u64 t, %1; cvt.u32.u64 %0, t; }"
        : "=r"(a) : "l"(p));
    return a;
}
__device__ __forceinline__ void ldsm4(uint32_t* r, uint32_t addr) {
    asm volatile("ldmatrix.sync.aligned.m8n8.x4.shared.b16 {%0,%1,%2,%3}, [%4];"
        : "=r"(r[0]), "=r"(r[1]), "=r"(r[2]), "=r"(r[3]) : "r"(addr));
}
__device__ __forceinline__ void ldsm4t(uint32_t* r, uint32_t addr) {
    asm volatile("ldmatrix.sync.aligned.m8n8.x4.trans.shared.b16 {%0,%1,%2,%3}, [%4];"
        : "=r"(r[0]), "=r"(r[1]), "=r"(r[2]), "=r"(r[3]) : "r"(addr));
}
__device__ __forceinline__ void mma16816(float* c, const uint32_t* a,
                                         const uint32_t* b) {
    asm volatile("mma.sync.aligned.m16n8k16.row.col.f32.f16.f16.f32 "
        "{%0,%1,%2,%3}, {%4,%5,%6,%7}, {%8,%9}, {%0,%1,%2,%3};"
        : "+f"(c[0]), "+f"(c[1]), "+f"(c[2]), "+f"(c[3])
        : "r"(a[0]), "r"(a[1]), "r"(a[2]), "r"(a[3]), "r"(b[0]), "r"(b[1]));
}
__device__ __forceinline__ void cp16(uint32_t dst, const void* src) {
    asm volatile("cp.async.cg.shared.global [%0], [%1], 16;"
                 :: "r"(dst), "l"(src));
}
__device__ __forceinline__ void cp_commit() {
    asm volatile("cp.async.commit_group;" ::: "memory");
}
template <int N>
__device__ __forceinline__ void cp_wait() {
    asm volatile("cp.async.wait_group %0;" :: "n"(N) : "memory");
}
__device__ __forceinline__ uint32_t h2bits(float a, float b) {
    __half2 h = __floats2half2_rn(a, b);
    return *reinterpret_cast<uint32_t*>(&h);
}

// ---------------- cvt hidden -> fp16, + fused rope table & pool zero --------
__global__ __launch_bounds__(256) void cvt_kernel(const float4* __restrict__ x,
                                                  __half* __restrict__ y, int n4,
                                                  float2* __restrict__ rope,
                                                  float* __restrict__ pool) {
    int i = blockIdx.x * 256 + threadIdx.x;
    if (i < n4) {
        float4 v = x[i];
        uint2 o;
        o.x = h2bits(v.x, v.y);
        o.y = h2bits(v.z, v.w);
        *(uint2*)(y + (size_t)i * 4) = o;
    }
    if (blockIdx.x < 256) {
        int e = blockIdx.x * 256 + threadIdx.x;
        int pos = e >> 6, j = e & 63;
        double invf = exp(-(double)j * (9.210340371976184 / 64.0));
        double ang = (double)pos * invf;
        const double TWO_PI = 6.283185307179586476925286766559;
        ang -= floor(ang * (1.0 / TWO_PI)) * TWO_PI;
        float c, s;
        sincosf((float)ang, &s, &c);
        rope[e] = make_float2(c, s);
    }
    if (blockIdx.x == 300 && threadIdx.x < BATCH * HD) {
        pool[threadIdx.x] = 0.0f;
        pool[threadIdx.x + 256] = 0.0f;
    }
}

__global__ void cvt_T_kernel(const float* __restrict__ w,
                             __half* __restrict__ wT, int K, int N) {
    __shared__ __half sh[32][34];
    int tx = threadIdx.x, ty = threadIdx.y;
    int n0 = blockIdx.x * 32, k0 = blockIdx.y * 32;
    #pragma unroll
    for (int j = 0; j < 4; j++) {
        int k = k0 + ty + j * 8;
        sh[tx][ty + j * 8] = __float2half(w[(size_t)k * N + n0 + tx]);
    }
    __syncthreads();
    #pragma unroll
    for (int j = 0; j < 4; j++) {
        int n = n0 + ty + j * 8;
        wT[(size_t)n * K + k0 + tx] = sh[ty + j * 8][tx];
    }
}

// ---------------- fused Q+K rmsnorm+rope (fp16 in/out) ----------------------
// grid (T_TOK, 5): y<4 -> q heads [y*8, y*8+8); y==4 -> the 8 kv heads.
__global__ __launch_bounds__(256) void norm_fused(
    const __half* __restrict__ qkv, const int* __restrict__ positions,
    const float* __restrict__ qw, const float* __restrict__ kw,
    const float2* __restrict__ rope,
    __half* __restrict__ qh, __half* __restrict__ kh, float* __restrict__ pool) {
    int t = blockIdx.x;
    int lane = threadIdx.x & 31;
    int wz = threadIdx.x >> 5;
    int pos = positions[t];
    float2 cs0 = rope[pos * 64 + lane];
    float2 cs1 = rope[pos * 64 + lane + 32];

    if (blockIdx.y < 4) {
        int h = blockIdx.y * 8 + wz;
        __shared__ float spool[128];
        for (int i = threadIdx.x; i < 128; i += 256) spool[i] = 0.0f;
        __syncthreads();
        const __half* src = qkv + (size_t)t * QKV_OUT + h * HD;
        float x0 = __half2float(src[lane]);
        float x1 = __half2float(src[lane + 32]);
        float x2 = __half2float(src[lane + 64]);
        float x3 = __half2float(src[lane + 96]);
        float ss = x0 * x0 + x1 * x1 + x2 * x2 + x3 * x3;
        #pragma unroll
        for (int o = 16; o > 0; o >>= 1) ss += __shfl_xor_sync(0xffffffffu, ss, o);
        float r = rsqrtf(ss * (1.0f / 128.0f) + EPSF);
        float n0 = x0 * r * qw[lane];
        float n1 = x1 * r * qw[lane + 32];
        float n2 = x2 * r * qw[lane + 64];
        float n3 = x3 * r * qw[lane + 96];
        atomicAdd(&spool[lane],      n0);
        atomicAdd(&spool[lane + 32], n1);
        atomicAdd(&spool[lane + 64], n2);
        atomicAdd(&spool[lane + 96], n3);
        float o0 = n0 * cs0.x - n2 * cs0.y;
        float o2 = n2 * cs0.x + n0 * cs0.y;
        float o1 = n1 * cs1.x - n3 * cs1.y;
        float o3 = n3 * cs1.x + n1 * cs1.y;
        size_t base = (size_t)t * (NH * HD) + h * HD;
        qh[base + lane]      = __float2half(o0);
        qh[base + lane + 32] = __float2half(o1);
        qh[base + lane + 64] = __float2half(o2);
        qh[base + lane + 96] = __float2half(o3);
        __syncthreads();
        if (threadIdx.x < 128)
            atomicAdd(&pool[(t / SEQ) * 128 + threadIdx.x], spool[threadIdx.x]);
    } else {
        int h = wz;
        const __half* src = qkv + (size_t)t * QKV_OUT + NH * HD + h * HD;
        float x0 = __half2float(src[lane]);
        float x1 = __half2float(src[lane + 32]);
        float x2 = __half2float(src[lane + 64]);
        float x3 = __half2float(src[lane + 96]);
        float ss = x0 * x0 + x1 * x1 + x2 * x2 + x3 * x3;
        #pragma unroll
        for (int o = 16; o > 0; o >>= 1) ss += __shfl_xor_sync(0xffffffffu, ss, o);
        float r = rsqrtf(ss * (1.0f / 128.0f) + EPSF);
        float n0 = x0 * r * kw[lane];
        float n1 = x1 * r * kw[lane + 32];
        float n2 = x2 * r * kw[lane + 64];
        float n3 = x3 * r * kw[lane + 96];
        float o0 = n0 * cs0.x - n2 * cs0.y;
        float o2 = n2 * cs0.x + n0 * cs0.y;
        float o1 = n1 * cs1.x - n3 * cs1.y;
        float o3 = n3 * cs1.x + n1 * cs1.y;
        size_t base = (size_t)t * (NKV * HD) + h * HD;
        kh[base + lane]      = __float2half(o0);
        kh[base + lane + 32] = __float2half(o1);
        kh[base + lane + 64] = __float2half(o2);
        kh[base + lane + 96] = __float2half(o3);
    }
}

// ---------------- router gate ----------------
__device__ __forceinline__ float silu_f(float x) { return x / (1.0f + expf(-x)); }

__global__ __launch_bounds__(256) void router_kernel(
    const float* __restrict__ pool,
    const float* __restrict__ w1, const float* __restrict__ b1,
    const float* __restrict__ w2, const float* __restrict__ b2,
    const float* __restrict__ w3, const float* __restrict__ b3,
    const float* __restrict__ w4, const float* __restrict__ b4,
    const float* __restrict__ w5, const float* __restrict__ b5,
    float* __restrict__ gate) {
    __shared__ float pm[4][128];
    __shared__ float h1[4][1024];
    __shared__ float h2[4][256];
    __shared__ float h3[4][512];
    __shared__ float h4[4][128];
    __shared__ int anyflag;
    int tid = threadIdx.x;
    if (tid == 0) anyflag = 0;
    for (int idx = tid; idx < 512; idx += 256)
        pm[idx >> 7][idx & 127] = pool[idx] * (1.0f / 32768.0f);
    __syncthreads();
    for (int idx = tid; idx < 4096; idx += 256) {
        int b = idx >> 10, n = idx & 1023;
        float a = b1[n];
        for (int k = 0; k < 128; k++) a += pm[b][k] * w1[k * 1024 + n];
        h1[b][n] = silu_f(a);
    }
    __syncthreads();
    for (int idx = tid; idx < 1024; idx += 256) {
        int b = idx >> 8, n = idx & 255;
        float a = b2[n];
        for (int k = 0; k < 1024; k++) a += h1[b][k] * w2[k * 256 + n];
        h2[b][n] = a;
    }
    __syncthreads();
    for (int idx = tid; idx < 2048; idx += 256) {
        int b = idx >> 9, n = idx & 511;
        float a = b3[n];
        for (int k = 0; k < 256; k++) a += h2[b][k] * w3[k * 512 + n];
        h3[b][n] = silu_f(a);
    }
    __syncthreads();
    for (int idx = tid; idx < 512; idx += 256) {
        int b = idx >> 7, n = idx & 127;
        float a = b4[n];
        for (int k = 0; k < 512; k++) a += h3[b][k] * w4[k * 128 + n];
        h4[b][n] = silu_f(a);
    }
    __syncthreads();
    if (tid < 4) {
        float l0 = b5[0], l1 = b5[1];
        for (int k = 0; k < 128; k++) {
            l0 += h4[tid][k] * w5[k * 2 + 0];
            l1 += h4[tid][k] * w5[k * 2 + 1];
        }
        if (l1 > l0) anyflag = 1;
    }
    __syncthreads();
    if (tid == 0) gate[0] = anyflag ? 1.0f : 0.0f;
}

// ---------------- warp-MMA fp16 GEMM v7: fragment double-buffering ----------
// CTA 128x128, BK=64, 128 thr / 4 warps (2m x 2n), warp tile 64x64, 3-stage
// cp.async ring, 2 CTAs/SM. NEW: ldsm fragments for slice ks+1 issued BEFORE
// the slice-ks mma block (double-buffered in regs) so ldsm latency overlaps
// tensor work instead of stalling it.
#define ROWB 144
#define ABUF (128 * ROWB)
#define STGB (2 * ABUF)
#define NSTG 3
#define GEMM_SMEM (NSTG * STGB)
__global__ __launch_bounds__(128, 2) void gemm_fp16_mma(
    const __half* __restrict__ A, const __half* __restrict__ B,
    void* __restrict__ C, int N, int K, int halfout) {
    extern __shared__ __align__(16) char smem[];
    uint32_t sb = smem_u32(smem);
    int tid = threadIdx.x, wid = tid >> 5, lane = tid & 31;
    int wm = wid >> 1, wn = wid & 1;
    size_t bm = blockIdx.y, bn = blockIdx.x;
    int NT = K >> 6;

    int rA = tid >> 3, ch = tid & 7;
    const __half* srcA = A + (bm * 128 + rA) * (size_t)K + ch * 8;
    const __half* srcB = B + (bn * 128 + rA) * (size_t)K + ch * 8;
    uint32_t dA = (uint32_t)(rA * ROWB + ch * 16);

    uint32_t aoff = (uint32_t)((wm * 64 + (lane & 15)) * ROWB + ((lane >> 4) << 4));
    int g = lane >> 3;
    uint32_t boff = (uint32_t)((wn * 64 + ((g >> 1) << 3) + (lane & 7)) * ROWB +
                               ((g & 1) << 4));

    float acc[4][8][4];
    #pragma unroll
    for (int i = 0; i < 4; i++)
        #pragma unroll
        for (int j = 0; j < 8; j++)
            #pragma unroll
            for (int q = 0; q < 4; q++) acc[i][j][q] = 0.0f;

    #pragma unroll
    for (int pstg = 0; pstg < 2; pstg++) {
        uint32_t db = sb + pstg * STGB;
        #pragma unroll
        for (int i = 0; i < 8; i++) {
            cp16(db + dA + i * (16 * ROWB), srcA + (size_t)i * 16 * K);
            cp16(db + ABUF + dA + i * (16 * ROWB), srcB + (size_t)i * 16 * K);
        }
        srcA += 64; srcB += 64;
        cp_commit();
    }

    uint32_t af[2][4][4], bf[2][4][4];

    for (int kt = 0; kt < NT; kt++) {
        if (kt + 1 < NT) cp_wait<1>();
        else             cp_wait<0>();
        __syncthreads();
        if (kt + 2 < NT) {
            uint32_t db = sb + ((kt + 2) % 3) * STGB;
            #pragma unroll
            for (int i = 0; i < 8; i++) {
                cp16(db + dA + i * (16 * ROWB), srcA + (size_t)i * 16 * K);
                cp16(db + ABUF + dA + i * (16 * ROWB), srcB + (size_t)i * 16 * K);
            }
            srcA += 64; srcB += 64;
            cp_commit();
        }

        uint32_t sA = sb + (kt % 3) * STGB;
        uint32_t sB = sA + ABUF;

        // preload slice 0 fragments
        #pragma unroll
        for (int amt = 0; amt < 4; amt++)
            ldsm4(af[0][amt], sA + aoff + amt * (16 * ROWB));
        #pragma unroll
        for (int bnt = 0; bnt < 4; bnt++)
            ldsm4(bf[0][bnt], sB + boff + bnt * (16 * ROWB));

        #pragma unroll
        for (int ks = 0; ks < 4; ks++) {
            int cur = ks & 1, nxt = cur ^ 1;
            if (ks < 3) {
                uint32_t kb = (uint32_t)(ks + 1) * 32;
                #pragma unroll
                for (int amt = 0; amt < 4; amt++)
                    ldsm4(af[nxt][amt], sA + aoff + amt * (16 * ROWB) + kb);
                #pragma unroll
                for (int bnt = 0; bnt < 4; bnt++)
                    ldsm4(bf[nxt][bnt], sB + boff + bnt * (16 * ROWB) + kb);
            }
            #pragma unroll
            for (int amt = 0; amt < 4; amt++)
                #pragma unroll
                for (int bnt = 0; bnt < 4; bnt++) {
                    mma16816(acc[amt][2 * bnt],     af[cur][amt], &bf[cur][bnt][0]);
                    mma16816(acc[amt][2 * bnt + 1], af[cur][amt], &bf[cur][bnt][2]);
                }
        }
    }

    if (halfout) {
        __half* Ch = (__half*)C;
        #pragma unroll
        for (int amt = 0; amt < 4; amt++) {
            size_t row = bm * 128 + wm * 64 + amt * 16 + (lane >> 2);
            #pragma unroll
            for (int bnt = 0; bnt < 4; bnt++)
                #pragma unroll
                for (int hh = 0; hh < 2; hh++) {
                    size_t col = bn * 128 + wn * 64 + bnt * 16 + hh * 8 +
                                 (lane & 3) * 2;
                    float* a4 = acc[amt][2 * bnt + hh];
                    *(uint32_t*)(Ch + row * N + col) = h2bits(a4[0], a4[1]);
                    *(uint32_t*)(Ch + (row + 8) * N + col) = h2bits(a4[2], a4[3]);
                }
        }
    } else {
        float* Cf = (float*)C;
        #pragma unroll
        for (int amt = 0; amt < 4; amt++) {
            size_t row = bm * 128 + wm * 64 + amt * 16 + (lane >> 2);
            #pragma unroll
            for (int bnt = 0; bnt < 4; bnt++)
                #pragma unroll
                for (int hh = 0; hh < 2; hh++) {
                    size_t col = bn * 128 + wn * 64 + bnt * 16 + hh * 8 +
                                 (lane & 3) * 2;
                    float* a4 = acc[amt][2 * bnt + hh];
                    *(float2*)(Cf + row * N + col) = make_float2(a4[0], a4[1]);
                    *(float2*)(Cf + (row + 8) * N + col) = make_float2(a4[2], a4[3]);
                }
        }
    }
}

// ---------------- flash attention v6 (unchanged from round 16) --------------
#define AROW 272
#define ATILE (64 * AROW)
#define ASTG (2 * ATILE)
#define ATTN_SMEM (2 * ASTG)
__global__ __launch_bounds__(256, 1) void attn_mma_kernel(
    const __half* __restrict__ qh, const __half* __restrict__ kh,
    const __half* __restrict__ qkvh, const float* __restrict__ gate,
    __half* __restrict__ oout) {
    extern __shared__ __align__(16) char smem[];
    uint32_t sb = smem_u32(smem);
    int qb = blockIdx.x;
    int bh = blockIdx.y;
    int b = bh >> 5, h = bh & 31;
    int kvh = h >> 2;
    int q0 = qb * 128;
    int tid = threadIdx.x, wid = tid >> 5, lane = tid & 31;
    int lrow = tid >> 4, lch = tid & 15;

    #pragma unroll
    for (int it = 0; it < 8; it++) {
        int rr = lrow + it * 16;
        size_t off = ((size_t)(b * SEQ + q0 + rr)) * (NH * HD) + h * HD + lch * 8;
        cp16(sb + rr * AROW + lch * 16, qh + off);
    }
    cp_commit();
    cp_wait<0>();
    __syncthreads();

    uint32_t qf[8][4];
    {
        uint32_t aoffQ = (uint32_t)((wid * 16 + (lane & 15)) * AROW +
                                    ((lane >> 4) << 4));
        #pragma unroll
        for (int ks = 0; ks < 8; ks++)
            ldsm4(qf[ks], sb + aoffQ + ks * 32);
    }
    __syncthreads();

    float of[16][4];
    #pragma unroll
    for (int i = 0; i < 16; i++)
        #pragma unroll
        for (int j = 0; j < 4; j++) of[i][j] = 0.0f;
    float m0 = -INFINITY, m1 = -INFINITY, l0 = 0.0f, l1 = 0.0f;
    int qi0 = q0 + wid * 16 + (lane >> 2);
    int qi1 = qi0 + 8;
    int numt = qb * 2 + 2;

    int g2 = lane >> 3;
    uint32_t boffK = (uint32_t)((((g2 >> 1) << 3) + (lane & 7)) * AROW +
                                ((g2 & 1) << 4));
    uint32_t vrow_base = (uint32_t)((((lane >> 3) & 1) * 8 + (lane & 7)) * AROW);
    uint32_t vcol_base = (uint32_t)((lane >> 4) << 4);

    const __half* vsrc = qkvh + (NH * HD + NKV * HD) + kvh * HD;

    #pragma unroll
    for (int it = 0; it < 4; it++) {
        int rr = lrow + it * 16;
        cp16(sb + rr * AROW + lch * 16,
             kh + ((size_t)(b * SEQ + rr)) * (NKV * HD) + kvh * HD + lch * 8);
        cp16(sb + ATILE + rr * AROW + lch * 16,
             vsrc + ((size_t)(b * SEQ + rr)) * QKV_OUT + lch * 8);
    }
    cp_commit();

    for (int kt = 0; kt < numt; kt++) {
        int k0 = kt * 64;
        __syncthreads();
        if (kt + 1 < numt) {
            uint32_t db = sb + ((kt + 1) & 1) * ASTG;
            int kn = (kt + 1) * 64;
            #pragma unroll
            for (int it = 0; it < 4; it++) {
                int rr = lrow + it * 16;
                cp16(db + rr * AROW + lch * 16,
                     kh + ((size_t)(b * SEQ + kn + rr)) * (NKV * HD) +
                     kvh * HD + lch * 8);
                cp16(db + ATILE + rr * AROW + lch * 16,
                     vsrc + ((size_t)(b * SEQ + kn + rr)) * QKV_OUT + lch * 8);
            }
            cp_commit();
            cp_wait<1>();
        } else {
            cp_wait<0>();
        }
        __syncthreads();

        uint32_t stg = sb + (kt & 1) * ASTG;
        uint32_t sK = stg, sV = stg + ATILE;

        float c[8][4];
        #pragma unroll
        for (int i = 0; i < 8; i++)
            #pragma unroll
            for (int j = 0; j < 4; j++) c[i][j] = 0.0f;
        #pragma unroll
        for (int ks = 0; ks < 8; ks++) {
            #pragma unroll
            for (int nf = 0; nf < 4; nf++) {
                uint32_t bh4[4];
                ldsm4(bh4, sK + boffK + nf * (16 * AROW) + ks * 32);
                mma16816(c[nf * 2],     qf[ks], bh4);
                mma16816(c[nf * 2 + 1], qf[ks], bh4 + 2);
            }
        }

        bool domask = (k0 + 63 > qi0);
        #pragma unroll
        for (int f = 0; f < 8; f++) {
            int kk = k0 + f * 8 + (lane & 3) * 2;
            c[f][0] *= ATT_SCALE;
            c[f][1] *= ATT_SCALE;
            c[f][2] *= ATT_SCALE;
            c[f][3] *= ATT_SCALE;
            if (domask) {
                if (kk > qi0)     c[f][0] = -INFINITY;
                if (kk + 1 > qi0) c[f][1] = -INFINITY;
                if (kk > qi1)     c[f][2] = -INFINITY;
                if (kk + 1 > qi1) c[f][3] = -INFINITY;
            }
        }

        float mx0 = -INFINITY, mx1 = -INFINITY;
        #pragma unroll
        for (int f = 0; f < 8; f++) {
            mx0 = fmaxf(mx0, fmaxf(c[f][0], c[f][1]));
            mx1 = fmaxf(mx1, fmaxf(c[f][2], c[f][3]));
        }
        mx0 = fmaxf(mx0, __shfl_xor_sync(0xffffffffu, mx0, 1));
        mx0 = fmaxf(mx0, __shfl_xor_sync(0xffffffffu, mx0, 2));
        mx1 = fmaxf(mx1, __shfl_xor_sync(0xffffffffu, mx1, 1));
        mx1 = fmaxf(mx1, __shfl_xor_sync(0xffffffffu, mx1, 2));
        float mn0 = fmaxf(m0, mx0), mn1 = fmaxf(m1, mx1);
        float co0 = expf(m0 - mn0), co1 = expf(m1 - mn1);
        float s0 = 0.0f, s1 = 0.0f;
        #pragma unroll
        for (int f = 0; f < 8; f++) {
            c[f][0] = expf(c[f][0] - mn0); s0 += c[f][0];
            c[f][1] = expf(c[f][1] - mn0); s0 += c[f][1];
            c[f][2] = expf(c[f][2] - mn1); s1 += c[f][2];
            c[f][3] = expf(c[f][3] - mn1); s1 += c[f][3];
        }
        s0 += __shfl_xor_sync(0xffffffffu, s0, 1);
        s0 += __shfl_xor_sync(0xffffffffu, s0, 2);
        s1 += __shfl_xor_sync(0xffffffffu, s1, 1);
        s1 += __shfl_xor_sync(0xffffffffu, s1, 2);
        l0 = l0 * co0 + s0;
        l1 = l1 * co1 + s1;
        m0 = mn0;
        m1 = mn1;
        #pragma unroll
        for (int f = 0; f < 16; f++) {
            of[f][0] *= co0;
            of[f][1] *= co0;
            of[f][2] *= co1;
            of[f][3] *= co1;
        }

        #pragma unroll
        for (int ks2 = 0; ks2 < 4; ks2++) {
            uint32_t a[4];
            a[0] = h2bits(c[2 * ks2][0],     c[2 * ks2][1]);
            a[1] = h2bits(c[2 * ks2][2],     c[2 * ks2][3]);
            a[2] = h2bits(c[2 * ks2 + 1][0], c[2 * ks2 + 1][1]);
            a[3] = h2bits(c[2 * ks2 + 1][2], c[2 * ks2 + 1][3]);
            uint32_t vbase = sV + vrow_base + ks2 * (16 * AROW) + vcol_base;
            #pragma unroll
            for (int df = 0; df < 8; df++) {
                uint32_t vb[4];
                ldsm4t(vb, vbase + df * 32);
                mma16816(of[df * 2],     a, vb);
                mma16816(of[df * 2 + 1], a, vb + 2);
            }
        }
    }

    float gi = gate[0];
    float inv0 = gi / l0, inv1 = gi / l1;
    size_t base0 = ((size_t)(b * SEQ + qi0)) * (NH * HD) + h * HD;
    size_t base1 = base0 + (size_t)8 * (NH * HD);
    #pragma unroll
    for (int df = 0; df < 8; df++) {
        #pragma unroll
        for (int hh = 0; hh < 2; hh++) {
            int dim = df * 16 + hh * 8 + (lane & 3) * 2;
            float* o4 = of[df * 2 + hh];
            *(uint32_t*)(oout + base0 + dim) = h2bits(o4[0] * inv0, o4[1] * inv0);
            *(uint32_t*)(oout + base1 + dim) = h2bits(o4[2] * inv1, o4[3] * inv1);
        }
    }
}

// ---------------- launch ----------------
// gemm_fp16_mma (QKV) at launch index 3 -> profiled: verify tensor% delta.
extern "C" void kernel_launch(void* const* d_in, const int* in_sizes, int n_in,
                              void* d_out, int out_size) {
    const float* hidden    = (const float*)d_in[0];
    const int*   positions = (const int*)d_in[1];
    const float* qkv_w = (const float*)d_in[3];
    const float* o_w   = (const float*)d_in[4];
    const float* qnw   = (const float*)d_in[5];
    const float* knw   = (const float*)d_in[6];
    const float* w1 = (const float*)d_in[7],  *b1 = (const float*)d_in[8];
    const float* w2 = (const float*)d_in[9],  *b2 = (const float*)d_in[10];
    const float* w3 = (const float*)d_in[11], *b3 = (const float*)d_in[12];
    const float* w4 = (const float*)d_in[13], *b4 = (const float*)d_in[14];
    const float* w5 = (const float*)d_in[15], *b5 = (const float*)d_in[16];
    float* out = (float*)d_out;

    float *pool, *gate;
    float2* rope;
    __half *hidh, *qwh, *owh, *qkvh, *qhp, *khp, *oh;
    cudaGetSymbolAddress((void**)&pool, g_pool);
    cudaGetSymbolAddress((void**)&gate, g_gate);
    cudaGetSymbolAddress((void**)&rope, g_rope);
    cudaGetSymbolAddress((void**)&hidh, g_hid);
    cudaGetSymbolAddress((void**)&qwh,  g_qw);
    cudaGetSymbolAddress((void**)&owh,  g_ow);
    cudaGetSymbolAddress((void**)&qkvh, g_qkvh);
    cudaGetSymbolAddress((void**)&qhp,  g_qh);
    cudaGetSymbolAddress((void**)&khp,  g_kh);
    cudaGetSymbolAddress((void**)&oh,   g_o);

    cudaFuncSetAttribute(gemm_fp16_mma,
                         cudaFuncAttributeMaxDynamicSharedMemorySize, GEMM_SMEM);
    cudaFuncSetAttribute(attn_mma_kernel,
                         cudaFuncAttributeMaxDynamicSharedMemorySize, ATTN_SMEM);

    int n4_hid = (T_TOK * HID) / 4;
    cvt_kernel<<<n4_hid / 256, 256>>>((const float4*)hidden, hidh, n4_hid,  // 0
                                      rope, pool);
    cvt_T_kernel<<<dim3(QKV_OUT / 32, HID / 32), dim3(32, 8)>>>(            // 1
        qkv_w, qwh, HID, QKV_OUT);
    cvt_T_kernel<<<dim3(HID / 32, HID / 32), dim3(32, 8)>>>(                // 2
        o_w, owh, HID, HID);

    gemm_fp16_mma<<<dim3(QKV_OUT / 128, T_TOK / 128), 128, GEMM_SMEM>>>(    // 3
        hidh, qwh, qkvh, QKV_OUT, HID, 1);

    norm_fused<<<dim3(T_TOK, 5), 256>>>(qkvh, positions, qnw, knw, rope,    // 4
                                        qhp, khp, pool);
    router_kernel<<<1, 256>>>(pool, w1, b1, w2, b2, w3, b3, w4, b4,         // 5
                              w5, b5, gate);
    attn_mma_kernel<<<dim3(SEQ / 128, BATCH * NH), 256, ATTN_SMEM>>>(       // 6
        qhp, khp, qkvh, gate, oh);

    gemm_fp16_mma<<<dim3(HID / 128, T_TOK / 128), 128, GEMM_SMEM>>>(        // 7
        oh, owh, out, HID, HID, 0);
}